// round 12
// baseline (speedup 1.0000x reference)
#include <cuda_runtime.h>
#include <cuda_bf16.h>
#include <math.h>
#include <stdint.h>

#define BATCH 4

__device__ __forceinline__ uint32_t smem_u32(const void* p){
    uint32_t a; asm("{ .reg .u64 t; cvta.to.shared.u64 t, %1; cvt.u32.u64 %0, t; }":"=r"(a):"l"(p)); return a;
}
__device__ __forceinline__ void ldsm4(uint32_t& r0, uint32_t& r1, uint32_t& r2, uint32_t& r3, uint32_t a){
    asm volatile("ldmatrix.sync.aligned.m8n8.x4.shared.b16 {%0,%1,%2,%3}, [%4];"
        :"=r"(r0),"=r"(r1),"=r"(r2),"=r"(r3):"r"(a));
}
__device__ __forceinline__ void mma16816(float* c, const uint32_t* a, const uint32_t* b){
    asm volatile("mma.sync.aligned.m16n8k16.row.col.f32.bf16.bf16.f32 "
        "{%0,%1,%2,%3}, {%4,%5,%6,%7}, {%8,%9}, {%0,%1,%2,%3};"
        : "+f"(c[0]),"+f"(c[1]),"+f"(c[2]),"+f"(c[3])
        : "r"(a[0]),"r"(a[1]),"r"(a[2]),"r"(a[3]),"r"(b[0]),"r"(b[1]));
}
__device__ __forceinline__ void cpasync16(uint32_t saddr, const void* g){
    asm volatile("cp.async.cg.shared.global [%0], [%1], 16;"::"r"(saddr),"l"(g));
}
__device__ __forceinline__ void cpcommit(){ asm volatile("cp.async.commit_group;"); }
__device__ __forceinline__ void cpwait0(){ asm volatile("cp.async.wait_group 0;"); }
__device__ __forceinline__ uint32_t packf(float v){
    __nv_bfloat16 h = __float2bfloat16(v);
    __nv_bfloat16 l = __float2bfloat16(v - __bfloat162float(h));
    return (uint32_t)*(unsigned short*)&h | ((uint32_t)*(unsigned short*)&l << 16);
}

// ---------------- scratch ----------------
__device__ float g_xd0[BATCH*1104*10*32];
__device__ float g_xd1[BATCH*552*20*64];
__device__ float g_ll1[BATCH*20*64];
__device__ float g_h1[BATCH*3*20*64];
__device__ float g_ll40[BATCH*40*128];
__device__ float g_mask1[BATCH*20*64];
__device__ float g_upm1[BATCH*20*64];
__device__ float g_cam1[BATCH*40*128];
__device__ float g_wm1[BATCH*40*128];
__device__ float g_xa[BATCH*276*40*128];
__device__ float g_h2[BATCH*3*40*128];
__device__ float g_ll80[BATCH*80*256];
__device__ float g_mask2[BATCH*40*128];
__device__ float g_upm2[BATCH*40*128];
__device__ float g_cam2[BATCH*80*256];
__device__ float g_wm2[BATCH*80*256];
__device__ float g_xb[BATCH*138*80*256];
__device__ float g_h3[BATCH*3*80*256];
__device__ float g_thr[1];
// packed u32 (bf16 hi | lo<<16) conv inputs
__device__ __align__(16) uint32_t g_px32[BATCH*2208*10*32];
__device__ __align__(16) uint32_t g_cat1[BATCH*1488*20*64];
__device__ __align__(16) uint32_t g_feat1[BATCH*744*40*128];
__device__ __align__(16) uint32_t g_feat0[BATCH*372*80*256];
// packed weights (hi/lo planes), K reordered as t*ICpad+ic
__device__ __align__(16) __nv_bfloat16 g_w2h[1152*19872];
__device__ __align__(16) __nv_bfloat16 g_w2l[1152*19872];
__device__ __align__(16) __nv_bfloat16 g_u1h[640*13536];
__device__ __align__(16) __nv_bfloat16 g_u1l[640*13536];
__device__ __align__(16) __nv_bfloat16 g_u2h[320*6912];
__device__ __align__(16) __nv_bfloat16 g_u2l[320*6912];
__device__ __align__(16) __nv_bfloat16 g_u3h[160*3456];
__device__ __align__(16) __nv_bfloat16 g_u3l[160*3456];

// ---------------- weight pack: w[oc, ic*9+t] -> planes[ocpad, t*ICpad+ic] ----------------
__global__ void pack_w_k(const float* __restrict__ w, __nv_bfloat16* __restrict__ hi,
                         __nv_bfloat16* __restrict__ lo, int OC, int IC, int ICpad, int Kpad, int totRC)
{
    int i = blockIdx.x*256 + threadIdx.x;
    if (i >= totRC) return;
    int t = blockIdx.y;
    int r = i / ICpad, ic = i - r*ICpad;
    float v = (r < OC && ic < IC) ? w[(size_t)r*IC*9 + ic*9 + t] : 0.f;
    __nv_bfloat16 h = __float2bfloat16(v);
    size_t o = (size_t)r*Kpad + t*ICpad + ic;
    hi[o] = h;
    lo[o] = __float2bfloat16(v - __bfloat162float(h));
}

// ---------------- input pack ----------------
__global__ void pack_x_k(const float* __restrict__ x, uint32_t* __restrict__ o, int total)
{
    int i = blockIdx.x*256 + threadIdx.x;
    if (i < total) o[i] = packf(x[i]);
}

// ---------------- zero accumulators ----------------
__global__ void zero6_k(float* a,int na, float* b,int nb, float* c,int nc,
                        float* d,int nd, float* e,int ne, float* f,int nf)
{
    int i = blockIdx.x*256 + threadIdx.x;
    if (i < na) a[i] = 0.f;
    if (i < nb) b[i] = 0.f;
    if (i < nc) c[i] = 0.f;
    if (i < nd) d[i] = 0.f;
    if (i < ne) e[i] = 0.f;
    if (i < nf) f[i] = 0.f;
}

// ---------------- feat build + pack ----------------
__global__ void feat_pack_k(const float* __restrict__ xc, const float* __restrict__ skip,
                            const float* __restrict__ upm, const float* __restrict__ cam,
                            uint32_t* __restrict__ out, int C1, int C2, int Hf, int Wf, int total)
{
    int idx = blockIdx.x*256 + threadIdx.x;
    if (idx >= total) return;
    int Wc = Wf >> 1, Hc = Hf >> 1;
    int x = idx % Wf; int t = idx / Wf;
    int y = t % Hf;  t /= Hf;
    int c = t % (C1+C2); int b = t / (C1+C2);
    float v;
    if (c < C1) {
        v = xc[((size_t)b*C1 + c)*Hc*Wc + (size_t)(y>>1)*Wc + (x>>1)];
        if (upm) v *= upm[(size_t)b*Hc*Wc + (size_t)(y>>1)*Wc + (x>>1)];
    } else {
        v = skip[((size_t)b*C2 + (c-C1))*Hf*Wf + (size_t)y*Wf + x];
    }
    if (cam) v *= cam[(size_t)b*Hf*Wf + (size_t)y*Wf + x];
    out[idx] = packf(v);
}

// ---------------- HMMA implicit-GEMM conv: K-chunk 32, double-buffered, 2 CTA/SM,
// staged gather, batch folded into N ----------------
#define ROWB 80
#define S_AH 0
#define S_AL 10240
#define S_BH 20480
#define S_BL 30720
#define BUFSZ 40960
#define CONV_SMEM (2*BUFSZ)

template<int PAD, int MT>  // PAD: 1 reflect, 2 edge. M-tile = 32*MT rows. MT in {1,2,4}.
__global__ __launch_bounds__(256, 2)
void conv_hmma(const __nv_bfloat16* __restrict__ Ah, const __nv_bfloat16* __restrict__ Al,
               const uint32_t* __restrict__ pin, float* __restrict__ out,
               int IC, int ICpad, int OC, int H, int W, int BHW, int Kpad, int S,
               const float* __restrict__ bias, const float* __restrict__ mask, int leaky)
{
    extern __shared__ __align__(16) unsigned char sm[];
    const uint32_t sb = smem_u32(sm);
    const int tid = threadIdx.x, wid = tid >> 5, lane = tid & 31;
    const int HW = H * W;
    const int n0 = blockIdx.x * 128;
    const int Mtiles = gridDim.y / S;
    const int mt_id = blockIdx.y % Mtiles, ks = blockIdx.y / Mtiles;
    const int m0 = mt_id * (32*MT);

    const int chunks = Kpad >> 5;
    const int cseg = (chunks + S - 1) / S;
    const int c0 = ks * cseg, c1 = min(chunks, c0 + cseg);

    const int wm = (wid >> 2) * (16*MT), wn = (wid & 3) * 32;

    float acc[MT][4][4];
    #pragma unroll
    for (int i=0;i<MT;i++) for (int j=0;j<4;j++) for (int k=0;k<4;k++) acc[i][j][k]=0.f;

    const int mloc = tid >> 1, kh = tid & 1;
    const int nglob = n0 + mloc;
    const bool okpix = (nglob < BHW);
    const int bix = okpix ? nglob / HW : 0;
    const int pix = okpix ? nglob - bix*HW : 0;
    const int py = pix / W, px_ = pix - (pix/W)*W;
    const uint32_t* inb = pin + (size_t)bix * IC * HW;

    int kthr = (c0 << 5) + kh*16;
    int tap = kthr / ICpad;
    int icr = kthr - tap*ICpad;

    uint32_t bv[16];   // staged B values; LDG latency overlapped with compute

    auto issueA = [&](int c, int bo){
        const int kc = c << 5;
        #pragma unroll
        for (int i = 0; i < MT; ++i) {
            int flat = i*256 + tid;
            int fo = flat * 16;
            int plane = fo / (MT*2048);
            int rem = fo - plane*(MT*2048);
            int row = rem >> 6, col = rem & 63;
            const __nv_bfloat16* src = (plane ? Al : Ah) + (size_t)(m0+row)*Kpad + kc + (col>>1);
            cpasync16(sb + bo + (plane ? S_AL : S_AH) + row*ROWB + col, src);
        }
        cpcommit();
    };
    auto gatherRegs = [&](){
        int t3 = (tap*11) >> 5;
        int dy = t3 - 1, dx = tap - t3*3 - 1;
        int yy = py + dy, xx = px_ + dx;
        if (PAD == 1) {
            yy = yy<0 ? -yy : (yy>=H ? 2*H-2-yy : yy);
            xx = xx<0 ? -xx : (xx>=W ? 2*W-2-xx : xx);
        } else {
            yy = min(max(yy,0),H-1); xx = min(max(xx,0),W-1);
        }
        const uint32_t* p = inb + (size_t)icr*HW + yy*W + xx;
        #pragma unroll
        for (int e = 0; e < 16; ++e)
            bv[e] = (okpix && (icr + e) < IC) ? __ldg(p + (size_t)e*HW) : 0u;
        icr += 32;
        if (icr >= ICpad) { icr -= ICpad; ++tap; }
    };
    auto stsB = [&](int bo){
        int d = bo + mloc*ROWB + kh*32;
        #pragma unroll
        for (int g8 = 0; g8 < 2; ++g8) {
            uint32_t* v = bv + g8*8;
            uint32_t hp0 = __byte_perm(v[0],v[1],0x5410), hp1 = __byte_perm(v[2],v[3],0x5410);
            uint32_t hp2 = __byte_perm(v[4],v[5],0x5410), hp3 = __byte_perm(v[6],v[7],0x5410);
            uint32_t lp0 = __byte_perm(v[0],v[1],0x7632), lp1 = __byte_perm(v[2],v[3],0x7632);
            uint32_t lp2 = __byte_perm(v[4],v[5],0x7632), lp3 = __byte_perm(v[6],v[7],0x7632);
            *(uint4*)(sm + d + S_BH + g8*16) = make_uint4(hp0,hp1,hp2,hp3);
            *(uint4*)(sm + d + S_BL + g8*16) = make_uint4(lp0,lp1,lp2,lp3);
        }
    };

    issueA(c0, 0);
    gatherRegs();

    for (int c = c0; c < c1; ++c) {
        const int bo = ((c - c0) & 1) * BUFSZ;
        const int bn = BUFSZ - bo;
        cpwait0();
        stsB(bo);
        __syncthreads();
        if (c + 1 < c1) {
            issueA(c + 1, bn);
            gatherRegs();
        }
        #pragma unroll
        for (int kk = 0; kk < 2; ++kk) {
            uint32_t bh[4][2], bl[4][2];
            #pragma unroll
            for (int nt2 = 0; nt2 < 2; ++nt2) {
                int g = lane >> 3;
                int brow = wn + nt2*16 + (lane & 7) + ((g & 2) ? 8 : 0);
                uint32_t baddr = sb + bo + brow*ROWB + kk*32 + ((g & 1) ? 16 : 0);
                ldsm4(bh[nt2*2][0], bh[nt2*2][1], bh[nt2*2+1][0], bh[nt2*2+1][1], baddr + S_BH);
                ldsm4(bl[nt2*2][0], bl[nt2*2][1], bl[nt2*2+1][0], bl[nt2*2+1][1], baddr + S_BL);
            }
            #pragma unroll
            for (int mt = 0; mt < MT; ++mt) {
                int arow = wm + mt*16 + (lane & 15);
                uint32_t aaddr = sb + bo + arow*ROWB + kk*32 + ((lane >> 4) ? 16 : 0);
                uint32_t ah[4], al[4];
                ldsm4(ah[0], ah[1], ah[2], ah[3], aaddr + S_AH);
                ldsm4(al[0], al[1], al[2], al[3], aaddr + S_AL);
                #pragma unroll
                for (int nt = 0; nt < 4; ++nt) {
                    mma16816(acc[mt][nt], ah, bh[nt]);
                    mma16816(acc[mt][nt], ah, bl[nt]);
                    mma16816(acc[mt][nt], al, bh[nt]);
                }
            }
        }
    }

    // ---- epilogue (batch decoded per element) ----
    const bool direct = (S == 1);
    #pragma unroll
    for (int mt = 0; mt < MT; ++mt) {
        #pragma unroll
        for (int nt = 0; nt < 4; ++nt) {
            #pragma unroll
            for (int cr = 0; cr < 4; ++cr) {
                int r = wm + mt*16 + (lane >> 2) + ((cr >= 2) ? 8 : 0);
                int col = wn + nt*8 + (lane & 3)*2 + (cr & 1);
                int oc = m0 + r, pxg = n0 + col;
                if (oc < OC && pxg < BHW) {
                    int bb = pxg / HW, pp = pxg - bb*HW;
                    float v = acc[mt][nt][cr];
                    float* op = out + ((size_t)bb*OC + oc)*HW + pp;
                    if (direct) {
                        if (bias) v += bias[oc];
                        if (leaky) v = v > 0.f ? v : 0.2f*v;
                        if (mask) v *= mask[(size_t)bb*HW + pp];
                        *op = v;
                    } else {
                        atomicAdd(op, v);
                    }
                }
            }
        }
    }
}

// ---------------- finalize big ----------------
__global__ void finalize_big(float* __restrict__ buf, const float* __restrict__ bias,
                             const float* __restrict__ mask, int C, int HW, int leaky, int total)
{
    int i = blockIdx.x*256 + threadIdx.x;
    if (i >= total) return;
    int p = i % HW, t = i / HW, c = t % C, b = t / C;
    float v = buf[i] + bias[c];
    if (leaky) v = v > 0.f ? v : 0.2f*v;
    if (mask) v *= mask[(size_t)b*HW + p];
    buf[i] = v;
}

// ---------------- small conv partial ----------------
template<int NOUT, int PAD>
__global__ void conv_small_part(const float* __restrict__ in, const float* __restrict__ wgt,
                                float* __restrict__ acc, int IC, int nsp, int H, int W)
{
    int b = blockIdx.z, sp = blockIdx.y;
    int HW = H*W;
    int p = blockIdx.x*128 + threadIdx.x;
    if (p >= HW) return;
    int y = p / W, x = p - y*W;
    int icPer = (IC + nsp - 1)/nsp, ic0 = sp*icPer, ic1 = min(IC, ic0+icPer);
    float a[NOUT];
    #pragma unroll
    for (int j = 0; j < NOUT; ++j) a[j] = 0.f;
    const float* inb = in + (size_t)b*IC*HW;
    for (int ic = ic0; ic < ic1; ++ic) {
        const float* ip = inb + (size_t)ic*HW;
        const float* wp = wgt + (size_t)ic*9;
        #pragma unroll
        for (int t = 0; t < 9; ++t) {
            int yy = y + t/3 - 1, xx = x + t%3 - 1;
            float v;
            if (PAD == 0) v = (yy>=0 && yy<H && xx>=0 && xx<W) ? __ldg(ip + yy*W + xx) : 0.f;
            else { yy = min(max(yy,0),H-1); xx = min(max(xx,0),W-1); v = __ldg(ip + yy*W + xx); }
            #pragma unroll
            for (int j = 0; j < NOUT; ++j)
                a[j] = fmaf(v, __ldg(wp + (size_t)j*IC*9 + t), a[j]);
        }
    }
    #pragma unroll
    for (int j = 0; j < NOUT; ++j)
        atomicAdd(acc + ((size_t)b*NOUT + j)*HW + p, a[j]);
}

__global__ void finalize_small(float* __restrict__ buf, const float* __restrict__ bias,
                               const float* __restrict__ mask, int NOUT, int H, int W,
                               float scale, int total)
{
    int i = blockIdx.x*256 + threadIdx.x;
    if (i >= total) return;
    int HW = H*W;
    int p = i % HW, t = i / HW, c = t % NOUT, b = t / NOUT;
    float v = (buf[i] + bias[c]) * scale;
    if (mask) {
        int y = p / W, x = p - y*W;
        v *= mask[(size_t)b*(HW/4) + (y>>1)*(W>>1) + (x>>1)];
    }
    buf[i] = v;
}

// ---------------- glue ----------------
__global__ void idwt_k(const float* __restrict__ ll, const float* __restrict__ h,
                       float* __restrict__ out, int Hc, int Wc)
{
    int b = blockIdx.z;
    int p = blockIdx.x*256 + threadIdx.x;
    if (p >= Hc*Wc) return;
    int y = p / Wc, x = p - y*Wc;
    float l = ll[(size_t)b*Hc*Wc + p];
    const float* hb = h + (size_t)b*3*Hc*Wc;
    float lh = hb[p], hl = hb[Hc*Wc+p], hh = hb[2*Hc*Wc+p];
    float a = (l+lh)*0.5f, c2 = (l-lh)*0.5f, d2 = (hl+hh)*0.5f, e = (hl-hh)*0.5f;
    float* ob = out + (size_t)b*(2*Hc)*(2*Wc);
    int W2 = 2*Wc;
    ob[(size_t)(2*y)*W2 + 2*x]     = a + d2;
    ob[(size_t)(2*y)*W2 + 2*x+1]   = c2 + e;
    ob[(size_t)(2*y+1)*W2 + 2*x]   = a - d2;
    ob[(size_t)(2*y+1)*W2 + 2*x+1] = c2 - e;
}
__global__ void minmax_k(const float* __restrict__ d, int n, float* __restrict__ thr)
{
    __shared__ float smn[1024], smx[1024];
    int tid = threadIdx.x;
    float mn = 3.4e38f, mx = -3.4e38f;
    for (int i = tid; i < n; i += 1024) { float v = d[i]; mn = fminf(mn,v); mx = fmaxf(mx,v); }
    smn[tid]=mn; smx[tid]=mx; __syncthreads();
    for (int s=512; s>0; s>>=1) {
        if (tid<s){ smn[tid]=fminf(smn[tid],smn[tid+s]); smx[tid]=fmaxf(smx[tid],smx[tid+s]); }
        __syncthreads();
    }
    if (tid==0) thr[0] = (smx[0]-smn[0])*0.1f;
}
__global__ void mask_k(const float* __restrict__ h, const float* __restrict__ thr,
                       float* __restrict__ mask, int Hc, int Wc)
{
    int b = blockIdx.z;
    int p = blockIdx.x*256 + threadIdx.x;
    if (p >= Hc*Wc) return;
    const float* hb = h + (size_t)b*3*Hc*Wc;
    float m = fmaxf(fabsf(hb[p]), fmaxf(fabsf(hb[Hc*Wc+p]), fabsf(hb[2*Hc*Wc+p])));
    mask[(size_t)b*Hc*Wc + p] = (m > thr[0]) ? 1.f : 0.f;
}
__global__ void pool_coarse_k(const float* __restrict__ mask, float* __restrict__ upm, int Hc, int Wc)
{
    int b = blockIdx.z;
    int p = blockIdx.x*256 + threadIdx.x;
    if (p >= Hc*Wc) return;
    int y = p / Wc, x = p - y*Wc;
    const float* mb = mask + (size_t)b*Hc*Wc;
    float r = 0.f;
    for (int dy=-2;dy<=2;dy++){ int yy=y+dy; if (yy<0||yy>=Hc) continue;
      for (int dx=-2;dx<=2;dx++){ int xx=x+dx; if (xx<0||xx>=Wc) continue;
        r = fmaxf(r, mb[yy*Wc+xx]); } }
    upm[(size_t)b*Hc*Wc + p] = (r > 0.f) ? 1.f : 0.f;
}
__global__ void pool_fine_k(const float* __restrict__ mask, float* __restrict__ cam,
                            float* __restrict__ wm, int Hc, int Wc)
{
    int b = blockIdx.z;
    int Hf = 2*Hc, Wf = 2*Wc;
    int p = blockIdx.x*256 + threadIdx.x;
    if (p >= Hf*Wf) return;
    int y = p / Wf, x = p - y*Wf;
    const float* mb = mask + (size_t)b*Hc*Wc;
    float c5 = 0.f, c3 = 0.f;
    for (int dy=-2;dy<=2;dy++){ int fy=y+dy; if (fy<0||fy>=Hf) continue;
      for (int dx=-2;dx<=2;dx++){ int fx=x+dx; if (fx<0||fx>=Wf) continue;
        float v = mb[(fy>>1)*Wc + (fx>>1)];
        c5 = fmaxf(c5, v);
        if (dy>=-1 && dy<=1 && dx>=-1 && dx<=1) c3 = fmaxf(c3, v);
      } }
    cam[(size_t)b*Hf*Wf + p] = (c5 > 0.f) ? 1.f : 0.f;
    wm [(size_t)b*Hf*Wf + p] = (c3 > 0.f) ? 1.f : 0.f;
}

// =======================================================================
extern "C" void kernel_launch(void* const* d_in, const int* in_sizes, int n_in,
                              void* d_out, int out_size)
{
    const float* x32 = (const float*)d_in[0];
    const float* x16 = (const float*)d_in[1];
    const float* x8  = (const float*)d_in[2];
    const float* x4  = (const float*)d_in[3];
    const float* c2w = (const float*)d_in[4];  const float* c2b = (const float*)d_in[5];
    const float* u1w = (const float*)d_in[6];  const float* u1b = (const float*)d_in[7];
    const float* wllw= (const float*)d_in[8];  const float* wllb= (const float*)d_in[9];
    const float* w1w = (const float*)d_in[10]; const float* w1b = (const float*)d_in[11];
    const float* u2w = (const float*)d_in[12]; const float* u2b = (const float*)d_in[13];
    const float* w2w = (const float*)d_in[14]; const float* w2b = (const float*)d_in[15];
    const float* u3w = (const float*)d_in[16]; const float* u3b = (const float*)d_in[17];
    const float* w3w = (const float*)d_in[18]; const float* w3b = (const float*)d_in[19];

    float *xd0,*xd1,*ll1,*h1,*ll40,*mask1,*upm1,*cam1,*wm1;
    float *xa,*h2,*ll80,*mask2,*upm2,*cam2,*wm2,*xb,*h3,*thr;
    uint32_t *px32,*cat1,*feat1,*feat0;
    __nv_bfloat16 *w2h,*w2l,*p1h,*p1l,*p2h,*p2l,*p3h,*p3l;
    cudaGetSymbolAddress((void**)&xd0,g_xd0);   cudaGetSymbolAddress((void**)&xd1,g_xd1);
    cudaGetSymbolAddress((void**)&ll1,g_ll1);   cudaGetSymbolAddress((void**)&h1,g_h1);
    cudaGetSymbolAddress((void**)&ll40,g_ll40); cudaGetSymbolAddress((void**)&mask1,g_mask1);
    cudaGetSymbolAddress((void**)&upm1,g_upm1); cudaGetSymbolAddress((void**)&cam1,g_cam1);
    cudaGetSymbolAddress((void**)&wm1,g_wm1);   cudaGetSymbolAddress((void**)&xa,g_xa);
    cudaGetSymbolAddress((void**)&h2,g_h2);     cudaGetSymbolAddress((void**)&ll80,g_ll80);
    cudaGetSymbolAddress((void**)&mask2,g_mask2); cudaGetSymbolAddress((void**)&upm2,g_upm2);
    cudaGetSymbolAddress((void**)&cam2,g_cam2); cudaGetSymbolAddress((void**)&wm2,g_wm2);
    cudaGetSymbolAddress((void**)&xb,g_xb);     cudaGetSymbolAddress((void**)&h3,g_h3);
    cudaGetSymbolAddress((void**)&thr,g_thr);
    cudaGetSymbolAddress((void**)&px32,g_px32); cudaGetSymbolAddress((void**)&cat1,g_cat1);
    cudaGetSymbolAddress((void**)&feat1,g_feat1); cudaGetSymbolAddress((void**)&feat0,g_feat0);
    cudaGetSymbolAddress((void**)&w2h,g_w2h);   cudaGetSymbolAddress((void**)&w2l,g_w2l);
    cudaGetSymbolAddress((void**)&p1h,g_u1h);   cudaGetSymbolAddress((void**)&p1l,g_u1l);
    cudaGetSymbolAddress((void**)&p2h,g_u2h);   cudaGetSymbolAddress((void**)&p2l,g_u2l);
    cudaGetSymbolAddress((void**)&p3h,g_u3h);   cudaGetSymbolAddress((void**)&p3l,g_u3l);

    cudaFuncSetAttribute(conv_hmma<2,4>, cudaFuncAttributeMaxDynamicSharedMemorySize, CONV_SMEM);
    cudaFuncSetAttribute(conv_hmma<1,4>, cudaFuncAttributeMaxDynamicSharedMemorySize, CONV_SMEM);
    cudaFuncSetAttribute(conv_hmma<1,2>, cudaFuncAttributeMaxDynamicSharedMemorySize, CONV_SMEM);
    cudaFuncSetAttribute(conv_hmma<1,1>, cudaFuncAttributeMaxDynamicSharedMemorySize, CONV_SMEM);

    // launches 1-3 (profiled slot 4 = conv2)
    { int t=1152*2208; pack_w_k<<<dim3((t+255)/256,9),256>>>(c2w, w2h, w2l, 1104, 2208, 2208, 19872, t); }
    { int t=BATCH*2208*320; pack_x_k<<<(t+255)/256,256>>>(x32, px32, t); }
    zero6_k<<<(BATCH*552*1280+255)/256,256>>>(xd0, BATCH*1104*320, xd1, BATCH*552*1280,
                                              ll1, BATCH*1280, h1, BATCH*3*1280,
                                              h2, BATCH*3*5120, h3, BATCH*3*20480);

    // 4: conv2 (edge): 2208->1104, BHW=1280 (10 N-tiles exact), Mtiles=9, S=4
    conv_hmma<2,4><<<dim3(10, 9*4), 256, CONV_SMEM>>>(w2h, w2l, px32, xd0,
        2208, 2208, 1104, 10, 32, 1280, 19872, 4, nullptr, nullptr, 0);
    finalize_big<<<(BATCH*1104*320+255)/256,256>>>(xd0, c2b, nullptr, 1104, 320, 0, BATCH*1104*320);

    { int t=640*1504;  pack_w_k<<<dim3((t+255)/256,9),256>>>(u1w, p1h, p1l, 552, 1488, 1504, 13536, t); }
    { int t = BATCH*1488*20*64;
      feat_pack_k<<<(t+255)/256,256>>>(xd0, x16, nullptr, nullptr, cat1, 1104, 384, 20, 64, t); }
    // up1 (reflect): 1488->552, BHW=5120 (40 tiles), Mtiles=5, S=2
    conv_hmma<1,4><<<dim3(40, 5*2), 256, CONV_SMEM>>>(p1h, p1l, cat1, xd1,
        1488, 1504, 552, 20, 64, 5120, 13536, 2, nullptr, nullptr, 0);
    finalize_big<<<(BATCH*552*1280+255)/256,256>>>(xd1, u1b, nullptr, 552, 1280, 1, BATCH*552*1280);
    conv_small_part<1,2><<<dim3(10,12,BATCH),128>>>(xd1, wllw, ll1, 552, 12, 20, 64);
    conv_small_part<3,0><<<dim3(10,12,BATCH),128>>>(xd1, w1w, h1, 552, 12, 20, 64);
    finalize_small<<<(BATCH*1280+255)/256,256>>>(ll1, wllb, nullptr, 1, 20, 64, 8.f, BATCH*1280);
    finalize_small<<<(BATCH*3*1280+255)/256,256>>>(h1, w1b, nullptr, 3, 20, 64, 4.f, BATCH*3*1280);
    idwt_k<<<dim3(5,1,BATCH),256>>>(ll1, h1, ll40, 20, 64);
    minmax_k<<<1,1024>>>(ll40, BATCH*40*128, thr);
    mask_k<<<dim3(5,1,BATCH),256>>>(h1, thr, mask1, 20, 64);
    pool_coarse_k<<<dim3(5,1,BATCH),256>>>(mask1, upm1, 20, 64);
    pool_fine_k<<<dim3(20,1,BATCH),256>>>(mask1, cam1, wm1, 20, 64);

    { int t=320*768;   pack_w_k<<<dim3((t+255)/256,9),256>>>(u2w, p2h, p2l, 276, 744, 768, 6912, t); }
    { int t = BATCH*744*40*128;
      feat_pack_k<<<(t+255)/256,256>>>(xd1, x8, upm1, cam1, feat1, 552, 192, 40, 128, t); }
    // up2 (reflect): 744->276, BHW=20480 (160 tiles), M-tile 64, Mtiles=5 (320 rows), S=1, fused
    conv_hmma<1,2><<<dim3(160, 5), 256, CONV_SMEM>>>(p2h, p2l, feat1, xa,
        744, 768, 276, 40, 128, 20480, 6912, 1, u2b, wm1, 1);
    conv_small_part<3,0><<<dim3(40,8,BATCH),128>>>(xa, w2w, h2, 276, 8, 40, 128);
    finalize_small<<<(BATCH*3*5120+255)/256,256>>>(h2, w2b, mask1, 3, 40, 128, 2.f, BATCH*3*5120);
    idwt_k<<<dim3(20,1,BATCH),256>>>(ll40, h2, ll80, 40, 128);
    minmax_k<<<1,1024>>>(ll80, BATCH*80*256, thr);
    mask_k<<<dim3(20,1,BATCH),256>>>(h2, thr, mask2, 40, 128);
    pool_coarse_k<<<dim3(20,1,BATCH),256>>>(mask2, upm2, 40, 128);
    pool_fine_k<<<dim3(80,1,BATCH),256>>>(mask2, cam2, wm2, 40, 128);

    { int t=160*384;   pack_w_k<<<dim3((t+255)/256,9),256>>>(u3w, p3h, p3l, 138, 372, 384, 3456, t); }
    { int t = BATCH*372*80*256;
      feat_pack_k<<<(t+255)/256,256>>>(xa, x4, upm2, cam2, feat0, 276, 96, 80, 256, t); }
    // up3 (reflect): 372->138, BHW=81920 (640 tiles), M-tile 32, Mtiles=5 (160 rows), S=1, fused
    conv_hmma<1,1><<<dim3(640, 5), 256, CONV_SMEM>>>(p3h, p3l, feat0, xb,
        372, 384, 138, 80, 256, 81920, 3456, 1, u3b, wm2, 1);
    conv_small_part<3,0><<<dim3(160,4,BATCH),128>>>(xb, w3w, h3, 138, 4, 80, 256);
    finalize_small<<<(BATCH*3*20480+255)/256,256>>>(h3, w3b, mask2, 3, 80, 256, 1.f, BATCH*3*20480);
    idwt_k<<<dim3(80,1,BATCH),256>>>(ll80, h3, (float*)d_out, 80, 256);
}

// round 13
// speedup vs baseline: 1.0337x; 1.0337x over previous
#include <cuda_runtime.h>
#include <cuda_bf16.h>
#include <math.h>
#include <stdint.h>

#define BATCH 4

__device__ __forceinline__ uint32_t smem_u32(const void* p){
    uint32_t a; asm("{ .reg .u64 t; cvta.to.shared.u64 t, %1; cvt.u32.u64 %0, t; }":"=r"(a):"l"(p)); return a;
}
__device__ __forceinline__ void ldsm4(uint32_t& r0, uint32_t& r1, uint32_t& r2, uint32_t& r3, uint32_t a){
    asm volatile("ldmatrix.sync.aligned.m8n8.x4.shared.b16 {%0,%1,%2,%3}, [%4];"
        :"=r"(r0),"=r"(r1),"=r"(r2),"=r"(r3):"r"(a));
}
__device__ __forceinline__ void mma16816(float* c, const uint32_t* a, const uint32_t* b){
    asm volatile("mma.sync.aligned.m16n8k16.row.col.f32.bf16.bf16.f32 "
        "{%0,%1,%2,%3}, {%4,%5,%6,%7}, {%8,%9}, {%0,%1,%2,%3};"
        : "+f"(c[0]),"+f"(c[1]),"+f"(c[2]),"+f"(c[3])
        : "r"(a[0]),"r"(a[1]),"r"(a[2]),"r"(a[3]),"r"(b[0]),"r"(b[1]));
}
__device__ __forceinline__ void cpasync16(uint32_t saddr, const void* g){
    asm volatile("cp.async.cg.shared.global [%0], [%1], 16;"::"r"(saddr),"l"(g));
}
__device__ __forceinline__ void cpcommit(){ asm volatile("cp.async.commit_group;"); }
__device__ __forceinline__ void cpwait0(){ asm volatile("cp.async.wait_group 0;"); }
__device__ __forceinline__ uint32_t packf(float v){
    __nv_bfloat16 h = __float2bfloat16(v);
    __nv_bfloat16 l = __float2bfloat16(v - __bfloat162float(h));
    return (uint32_t)*(unsigned short*)&h | ((uint32_t)*(unsigned short*)&l << 16);
}

// ---------------- scratch ----------------
__device__ float g_xd0[BATCH*1104*10*32];
__device__ float g_xd1[BATCH*552*20*64];
__device__ float g_ll1[BATCH*20*64];
__device__ float g_h1[BATCH*3*20*64];
__device__ float g_ll40[BATCH*40*128];
__device__ float g_mask1[BATCH*20*64];
__device__ float g_upm1[BATCH*20*64];
__device__ float g_cam1[BATCH*40*128];
__device__ float g_wm1[BATCH*40*128];
__device__ float g_xa[BATCH*276*40*128];
__device__ float g_h2[BATCH*3*40*128];
__device__ float g_ll80[BATCH*80*256];
__device__ float g_mask2[BATCH*40*128];
__device__ float g_upm2[BATCH*40*128];
__device__ float g_cam2[BATCH*80*256];
__device__ float g_wm2[BATCH*80*256];
__device__ float g_xb[BATCH*138*80*256];
__device__ float g_h3[BATCH*3*80*256];
__device__ float g_thr[1];
// packed u32 (bf16 hi | lo<<16) conv inputs
__device__ __align__(16) uint32_t g_px32[BATCH*2208*10*32];
__device__ __align__(16) uint32_t g_cat1[BATCH*1488*20*64];
__device__ __align__(16) uint32_t g_feat1[BATCH*744*40*128];
__device__ __align__(16) uint32_t g_feat0[BATCH*372*80*256];
// packed weights (hi/lo planes), K reordered as t*ICpad+ic
__device__ __align__(16) __nv_bfloat16 g_w2h[1152*19872];
__device__ __align__(16) __nv_bfloat16 g_w2l[1152*19872];
__device__ __align__(16) __nv_bfloat16 g_u1h[640*13536];
__device__ __align__(16) __nv_bfloat16 g_u1l[640*13536];
__device__ __align__(16) __nv_bfloat16 g_u2h[320*6912];
__device__ __align__(16) __nv_bfloat16 g_u2l[320*6912];
__device__ __align__(16) __nv_bfloat16 g_u3h[160*3456];
__device__ __align__(16) __nv_bfloat16 g_u3l[160*3456];

// ---------------- weight pack: w[oc, ic*9+t] -> planes[ocpad, t*ICpad+ic] ----------------
__global__ void pack_w_k(const float* __restrict__ w, __nv_bfloat16* __restrict__ hi,
                         __nv_bfloat16* __restrict__ lo, int OC, int IC, int ICpad, int Kpad, int totRC)
{
    int i = blockIdx.x*256 + threadIdx.x;
    if (i >= totRC) return;
    int t = blockIdx.y;
    int r = i / ICpad, ic = i - r*ICpad;
    float v = (r < OC && ic < IC) ? w[(size_t)r*IC*9 + ic*9 + t] : 0.f;
    __nv_bfloat16 h = __float2bfloat16(v);
    size_t o = (size_t)r*Kpad + t*ICpad + ic;
    hi[o] = h;
    lo[o] = __float2bfloat16(v - __bfloat162float(h));
}

// ---------------- input pack ----------------
__global__ void pack_x_k(const float* __restrict__ x, uint32_t* __restrict__ o, int total)
{
    int i = blockIdx.x*256 + threadIdx.x;
    if (i < total) o[i] = packf(x[i]);
}

// ---------------- zero accumulators ----------------
__global__ void zero6_k(float* a,int na, float* b,int nb, float* c,int nc,
                        float* d,int nd, float* e,int ne, float* f,int nf)
{
    int i = blockIdx.x*256 + threadIdx.x;
    if (i < na) a[i] = 0.f;
    if (i < nb) b[i] = 0.f;
    if (i < nc) c[i] = 0.f;
    if (i < nd) d[i] = 0.f;
    if (i < ne) e[i] = 0.f;
    if (i < nf) f[i] = 0.f;
}

// ---------------- feat build + pack ----------------
__global__ void feat_pack_k(const float* __restrict__ xc, const float* __restrict__ skip,
                            const float* __restrict__ upm, const float* __restrict__ cam,
                            uint32_t* __restrict__ out, int C1, int C2, int Hf, int Wf, int total)
{
    int idx = blockIdx.x*256 + threadIdx.x;
    if (idx >= total) return;
    int Wc = Wf >> 1, Hc = Hf >> 1;
    int x = idx % Wf; int t = idx / Wf;
    int y = t % Hf;  t /= Hf;
    int c = t % (C1+C2); int b = t / (C1+C2);
    float v;
    if (c < C1) {
        v = xc[((size_t)b*C1 + c)*Hc*Wc + (size_t)(y>>1)*Wc + (x>>1)];
        if (upm) v *= upm[(size_t)b*Hc*Wc + (size_t)(y>>1)*Wc + (x>>1)];
    } else {
        v = skip[((size_t)b*C2 + (c-C1))*Hf*Wf + (size_t)y*Wf + x];
    }
    if (cam) v *= cam[(size_t)b*Hf*Wf + (size_t)y*Wf + x];
    out[idx] = packf(v);
}

// ---------------- HMMA implicit-GEMM conv: K-chunk 32, double-buffered, 2 CTA/SM, staged gather ----------------
#define ROWB 80
#define S_AH 0
#define S_AL 10240
#define S_BH 20480
#define S_BL 30720
#define BUFSZ 40960
#define CONV_SMEM (2*BUFSZ)

template<int PAD, int MT>  // PAD: 1 reflect, 2 edge. M-tile = 32*MT rows.
__global__ __launch_bounds__(256, 2)
void conv_hmma(const __nv_bfloat16* __restrict__ Ah, const __nv_bfloat16* __restrict__ Al,
               const uint32_t* __restrict__ pin, float* __restrict__ out,
               int IC, int ICpad, int OC, int H, int W, int Kpad, int S, int m0base,
               const float* __restrict__ bias, const float* __restrict__ mask, int leaky)
{
    extern __shared__ __align__(16) unsigned char sm[];
    const uint32_t sb = smem_u32(sm);
    const int tid = threadIdx.x, wid = tid >> 5, lane = tid & 31;
    const int HW = H * W;
    const int n0 = blockIdx.x * 128;
    const int Mtiles = gridDim.y / S;
    const int mt_id = blockIdx.y % Mtiles, ks = blockIdx.y / Mtiles;
    const int m0 = m0base + mt_id * (32*MT);
    const int b = blockIdx.z;

    const int chunks = Kpad >> 5;
    const int cseg = (chunks + S - 1) / S;
    const int c0 = ks * cseg, c1 = min(chunks, c0 + cseg);

    const uint32_t* inb = pin + (size_t)b * IC * HW;
    const int wm = (wid >> 2) * (16*MT), wn = (wid & 3) * 32;

    float acc[MT][4][4];
    #pragma unroll
    for (int i=0;i<MT;i++) for (int j=0;j<4;j++) for (int k=0;k<4;k++) acc[i][j][k]=0.f;

    const int mloc = tid >> 1, kh = tid & 1;
    const int nglob = n0 + mloc;
    const bool okpix = (nglob < HW);
    const int py = okpix ? nglob / W : 0;
    const int px_ = okpix ? nglob - py*W : 0;

    int kthr = (c0 << 5) + kh*16;
    int tap = kthr / ICpad;
    int icr = kthr - tap*ICpad;

    uint32_t bv[16];   // staged B values; LDG latency overlapped with compute

    auto issueA = [&](int c, int bo){
        const int kc = c << 5;
        #pragma unroll
        for (int i = 0; i < MT; ++i) {
            int flat = i*256 + tid;
            int fo = flat * 16;
            int plane = fo / (MT*2048);
            int rem = fo - plane*(MT*2048);
            int row = rem >> 6, col = rem & 63;
            const __nv_bfloat16* src = (plane ? Al : Ah) + (size_t)(m0+row)*Kpad + kc + (col>>1);
            cpasync16(sb + bo + (plane ? S_AL : S_AH) + row*ROWB + col, src);
        }
        cpcommit();
    };
    auto gatherRegs = [&](){
        int t3 = (tap*11) >> 5;
        int dy = t3 - 1, dx = tap - t3*3 - 1;
        int yy = py + dy, xx = px_ + dx;
        if (PAD == 1) {
            yy = yy<0 ? -yy : (yy>=H ? 2*H-2-yy : yy);
            xx = xx<0 ? -xx : (xx>=W ? 2*W-2-xx : xx);
        } else {
            yy = min(max(yy,0),H-1); xx = min(max(xx,0),W-1);
        }
        const uint32_t* p = inb + (size_t)icr*HW + yy*W + xx;
        #pragma unroll
        for (int e = 0; e < 16; ++e)
            bv[e] = (okpix && (icr + e) < IC) ? __ldg(p + (size_t)e*HW) : 0u;
        icr += 32;
        if (icr >= ICpad) { icr -= ICpad; ++tap; }
    };
    auto stsB = [&](int bo){
        int d = bo + mloc*ROWB + kh*32;
        #pragma unroll
        for (int g8 = 0; g8 < 2; ++g8) {
            uint32_t* v = bv + g8*8;
            uint32_t hp0 = __byte_perm(v[0],v[1],0x5410), hp1 = __byte_perm(v[2],v[3],0x5410);
            uint32_t hp2 = __byte_perm(v[4],v[5],0x5410), hp3 = __byte_perm(v[6],v[7],0x5410);
            uint32_t lp0 = __byte_perm(v[0],v[1],0x7632), lp1 = __byte_perm(v[2],v[3],0x7632);
            uint32_t lp2 = __byte_perm(v[4],v[5],0x7632), lp3 = __byte_perm(v[6],v[7],0x7632);
            *(uint4*)(sm + d + S_BH + g8*16) = make_uint4(hp0,hp1,hp2,hp3);
            *(uint4*)(sm + d + S_BL + g8*16) = make_uint4(lp0,lp1,lp2,lp3);
        }
    };

    issueA(c0, 0);
    gatherRegs();

    for (int c = c0; c < c1; ++c) {
        const int bo = ((c - c0) & 1) * BUFSZ;
        const int bn = BUFSZ - bo;
        cpwait0();
        stsB(bo);
        __syncthreads();
        if (c + 1 < c1) {
            issueA(c + 1, bn);
            gatherRegs();
        }
        #pragma unroll
        for (int kk = 0; kk < 2; ++kk) {
            uint32_t bh[4][2], bl[4][2];
            #pragma unroll
            for (int nt2 = 0; nt2 < 2; ++nt2) {
                int g = lane >> 3;
                int brow = wn + nt2*16 + (lane & 7) + ((g & 2) ? 8 : 0);
                uint32_t baddr = sb + bo + brow*ROWB + kk*32 + ((g & 1) ? 16 : 0);
                ldsm4(bh[nt2*2][0], bh[nt2*2][1], bh[nt2*2+1][0], bh[nt2*2+1][1], baddr + S_BH);
                ldsm4(bl[nt2*2][0], bl[nt2*2][1], bl[nt2*2+1][0], bl[nt2*2+1][1], baddr + S_BL);
            }
            #pragma unroll
            for (int mt = 0; mt < MT; ++mt) {
                int arow = wm + mt*16 + (lane & 15);
                uint32_t aaddr = sb + bo + arow*ROWB + kk*32 + ((lane >> 4) ? 16 : 0);
                uint32_t ah[4], al[4];
                ldsm4(ah[0], ah[1], ah[2], ah[3], aaddr + S_AH);
                ldsm4(al[0], al[1], al[2], al[3], aaddr + S_AL);
                #pragma unroll
                for (int nt = 0; nt < 4; ++nt) {
                    mma16816(acc[mt][nt], ah, bh[nt]);
                    mma16816(acc[mt][nt], ah, bl[nt]);
                    mma16816(acc[mt][nt], al, bh[nt]);
                }
            }
        }
    }

    // ---- epilogue ----
    float* ob = out + (size_t)b * OC * HW;
    const float* mb = mask ? mask + (size_t)b*HW : nullptr;
    const bool direct = (S == 1);
    #pragma unroll
    for (int mt = 0; mt < MT; ++mt) {
        #pragma unroll
        for (int nt = 0; nt < 4; ++nt) {
            #pragma unroll
            for (int cr = 0; cr < 4; ++cr) {
                int r = wm + mt*16 + (lane >> 2) + ((cr >= 2) ? 8 : 0);
                int col = wn + nt*8 + (lane & 3)*2 + (cr & 1);
                int oc = m0 + r, px = n0 + col;
                if (oc < OC && px < HW) {
                    float v = acc[mt][nt][cr];
                    if (direct) {
                        if (bias) v += bias[oc];
                        if (leaky) v = v > 0.f ? v : 0.2f*v;
                        if (mb) v *= mb[px];
                        ob[(size_t)oc*HW + px] = v;
                    } else {
                        atomicAdd(ob + (size_t)oc*HW + px, v);
                    }
                }
            }
        }
    }
}

// ---------------- finalize big ----------------
__global__ void finalize_big(float* __restrict__ buf, const float* __restrict__ bias,
                             const float* __restrict__ mask, int C, int HW, int leaky, int total)
{
    int i = blockIdx.x*256 + threadIdx.x;
    if (i >= total) return;
    int p = i % HW, t = i / HW, c = t % C, b = t / C;
    float v = buf[i] + bias[c];
    if (leaky) v = v > 0.f ? v : 0.2f*v;
    if (mask) v *= mask[(size_t)b*HW + p];
    buf[i] = v;
}

// ---------------- small conv partial ----------------
template<int NOUT, int PAD>
__global__ void conv_small_part(const float* __restrict__ in, const float* __restrict__ wgt,
                                float* __restrict__ acc, int IC, int nsp, int H, int W)
{
    int b = blockIdx.z, sp = blockIdx.y;
    int HW = H*W;
    int p = blockIdx.x*128 + threadIdx.x;
    if (p >= HW) return;
    int y = p / W, x = p - y*W;
    int icPer = (IC + nsp - 1)/nsp, ic0 = sp*icPer, ic1 = min(IC, ic0+icPer);
    float a[NOUT];
    #pragma unroll
    for (int j = 0; j < NOUT; ++j) a[j] = 0.f;
    const float* inb = in + (size_t)b*IC*HW;
    for (int ic = ic0; ic < ic1; ++ic) {
        const float* ip = inb + (size_t)ic*HW;
        const float* wp = wgt + (size_t)ic*9;
        #pragma unroll
        for (int t = 0; t < 9; ++t) {
            int yy = y + t/3 - 1, xx = x + t%3 - 1;
            float v;
            if (PAD == 0) v = (yy>=0 && yy<H && xx>=0 && xx<W) ? __ldg(ip + yy*W + xx) : 0.f;
            else { yy = min(max(yy,0),H-1); xx = min(max(xx,0),W-1); v = __ldg(ip + yy*W + xx); }
            #pragma unroll
            for (int j = 0; j < NOUT; ++j)
                a[j] = fmaf(v, __ldg(wp + (size_t)j*IC*9 + t), a[j]);
        }
    }
    #pragma unroll
    for (int j = 0; j < NOUT; ++j)
        atomicAdd(acc + ((size_t)b*NOUT + j)*HW + p, a[j]);
}

__global__ void finalize_small(float* __restrict__ buf, const float* __restrict__ bias,
                               const float* __restrict__ mask, int NOUT, int H, int W,
                               float scale, int total)
{
    int i = blockIdx.x*256 + threadIdx.x;
    if (i >= total) return;
    int HW = H*W;
    int p = i % HW, t = i / HW, c = t % NOUT, b = t / NOUT;
    float v = (buf[i] + bias[c]) * scale;
    if (mask) {
        int y = p / W, x = p - y*W;
        v *= mask[(size_t)b*(HW/4) + (y>>1)*(W>>1) + (x>>1)];
    }
    buf[i] = v;
}

// ---------------- glue ----------------
__global__ void idwt_k(const float* __restrict__ ll, const float* __restrict__ h,
                       float* __restrict__ out, int Hc, int Wc)
{
    int b = blockIdx.z;
    int p = blockIdx.x*256 + threadIdx.x;
    if (p >= Hc*Wc) return;
    int y = p / Wc, x = p - y*Wc;
    float l = ll[(size_t)b*Hc*Wc + p];
    const float* hb = h + (size_t)b*3*Hc*Wc;
    float lh = hb[p], hl = hb[Hc*Wc+p], hh = hb[2*Hc*Wc+p];
    float a = (l+lh)*0.5f, c2 = (l-lh)*0.5f, d2 = (hl+hh)*0.5f, e = (hl-hh)*0.5f;
    float* ob = out + (size_t)b*(2*Hc)*(2*Wc);
    int W2 = 2*Wc;
    ob[(size_t)(2*y)*W2 + 2*x]     = a + d2;
    ob[(size_t)(2*y)*W2 + 2*x+1]   = c2 + e;
    ob[(size_t)(2*y+1)*W2 + 2*x]   = a - d2;
    ob[(size_t)(2*y+1)*W2 + 2*x+1] = c2 - e;
}
__global__ void minmax_k(const float* __restrict__ d, int n, float* __restrict__ thr)
{
    __shared__ float smn[1024], smx[1024];
    int tid = threadIdx.x;
    float mn = 3.4e38f, mx = -3.4e38f;
    for (int i = tid; i < n; i += 1024) { float v = d[i]; mn = fminf(mn,v); mx = fmaxf(mx,v); }
    smn[tid]=mn; smx[tid]=mx; __syncthreads();
    for (int s=512; s>0; s>>=1) {
        if (tid<s){ smn[tid]=fminf(smn[tid],smn[tid+s]); smx[tid]=fmaxf(smx[tid],smx[tid+s]); }
        __syncthreads();
    }
    if (tid==0) thr[0] = (smx[0]-smn[0])*0.1f;
}
__global__ void mask_k(const float* __restrict__ h, const float* __restrict__ thr,
                       float* __restrict__ mask, int Hc, int Wc)
{
    int b = blockIdx.z;
    int p = blockIdx.x*256 + threadIdx.x;
    if (p >= Hc*Wc) return;
    const float* hb = h + (size_t)b*3*Hc*Wc;
    float m = fmaxf(fabsf(hb[p]), fmaxf(fabsf(hb[Hc*Wc+p]), fabsf(hb[2*Hc*Wc+p])));
    mask[(size_t)b*Hc*Wc + p] = (m > thr[0]) ? 1.f : 0.f;
}
__global__ void pool_coarse_k(const float* __restrict__ mask, float* __restrict__ upm, int Hc, int Wc)
{
    int b = blockIdx.z;
    int p = blockIdx.x*256 + threadIdx.x;
    if (p >= Hc*Wc) return;
    int y = p / Wc, x = p - y*Wc;
    const float* mb = mask + (size_t)b*Hc*Wc;
    float r = 0.f;
    for (int dy=-2;dy<=2;dy++){ int yy=y+dy; if (yy<0||yy>=Hc) continue;
      for (int dx=-2;dx<=2;dx++){ int xx=x+dx; if (xx<0||xx>=Wc) continue;
        r = fmaxf(r, mb[yy*Wc+xx]); } }
    upm[(size_t)b*Hc*Wc + p] = (r > 0.f) ? 1.f : 0.f;
}
__global__ void pool_fine_k(const float* __restrict__ mask, float* __restrict__ cam,
                            float* __restrict__ wm, int Hc, int Wc)
{
    int b = blockIdx.z;
    int Hf = 2*Hc, Wf = 2*Wc;
    int p = blockIdx.x*256 + threadIdx.x;
    if (p >= Hf*Wf) return;
    int y = p / Wf, x = p - y*Wf;
    const float* mb = mask + (size_t)b*Hc*Wc;
    float c5 = 0.f, c3 = 0.f;
    for (int dy=-2;dy<=2;dy++){ int fy=y+dy; if (fy<0||fy>=Hf) continue;
      for (int dx=-2;dx<=2;dx++){ int fx=x+dx; if (fx<0||fx>=Wf) continue;
        float v = mb[(fy>>1)*Wc + (fx>>1)];
        c5 = fmaxf(c5, v);
        if (dy>=-1 && dy<=1 && dx>=-1 && dx<=1) c3 = fmaxf(c3, v);
      } }
    cam[(size_t)b*Hf*Wf + p] = (c5 > 0.f) ? 1.f : 0.f;
    wm [(size_t)b*Hf*Wf + p] = (c3 > 0.f) ? 1.f : 0.f;
}

// =======================================================================
extern "C" void kernel_launch(void* const* d_in, const int* in_sizes, int n_in,
                              void* d_out, int out_size)
{
    const float* x32 = (const float*)d_in[0];
    const float* x16 = (const float*)d_in[1];
    const float* x8  = (const float*)d_in[2];
    const float* x4  = (const float*)d_in[3];
    const float* c2w = (const float*)d_in[4];  const float* c2b = (const float*)d_in[5];
    const float* u1w = (const float*)d_in[6];  const float* u1b = (const float*)d_in[7];
    const float* wllw= (const float*)d_in[8];  const float* wllb= (const float*)d_in[9];
    const float* w1w = (const float*)d_in[10]; const float* w1b = (const float*)d_in[11];
    const float* u2w = (const float*)d_in[12]; const float* u2b = (const float*)d_in[13];
    const float* w2w = (const float*)d_in[14]; const float* w2b = (const float*)d_in[15];
    const float* u3w = (const float*)d_in[16]; const float* u3b = (const float*)d_in[17];
    const float* w3w = (const float*)d_in[18]; const float* w3b = (const float*)d_in[19];

    float *xd0,*xd1,*ll1,*h1,*ll40,*mask1,*upm1,*cam1,*wm1;
    float *xa,*h2,*ll80,*mask2,*upm2,*cam2,*wm2,*xb,*h3,*thr;
    uint32_t *px32,*cat1,*feat1,*feat0;
    __nv_bfloat16 *w2h,*w2l,*p1h,*p1l,*p2h,*p2l,*p3h,*p3l;
    cudaGetSymbolAddress((void**)&xd0,g_xd0);   cudaGetSymbolAddress((void**)&xd1,g_xd1);
    cudaGetSymbolAddress((void**)&ll1,g_ll1);   cudaGetSymbolAddress((void**)&h1,g_h1);
    cudaGetSymbolAddress((void**)&ll40,g_ll40); cudaGetSymbolAddress((void**)&mask1,g_mask1);
    cudaGetSymbolAddress((void**)&upm1,g_upm1); cudaGetSymbolAddress((void**)&cam1,g_cam1);
    cudaGetSymbolAddress((void**)&wm1,g_wm1);   cudaGetSymbolAddress((void**)&xa,g_xa);
    cudaGetSymbolAddress((void**)&h2,g_h2);     cudaGetSymbolAddress((void**)&ll80,g_ll80);
    cudaGetSymbolAddress((void**)&mask2,g_mask2); cudaGetSymbolAddress((void**)&upm2,g_upm2);
    cudaGetSymbolAddress((void**)&cam2,g_cam2); cudaGetSymbolAddress((void**)&wm2,g_wm2);
    cudaGetSymbolAddress((void**)&xb,g_xb);     cudaGetSymbolAddress((void**)&h3,g_h3);
    cudaGetSymbolAddress((void**)&thr,g_thr);
    cudaGetSymbolAddress((void**)&px32,g_px32); cudaGetSymbolAddress((void**)&cat1,g_cat1);
    cudaGetSymbolAddress((void**)&feat1,g_feat1); cudaGetSymbolAddress((void**)&feat0,g_feat0);
    cudaGetSymbolAddress((void**)&w2h,g_w2h);   cudaGetSymbolAddress((void**)&w2l,g_w2l);
    cudaGetSymbolAddress((void**)&p1h,g_u1h);   cudaGetSymbolAddress((void**)&p1l,g_u1l);
    cudaGetSymbolAddress((void**)&p2h,g_u2h);   cudaGetSymbolAddress((void**)&p2l,g_u2l);
    cudaGetSymbolAddress((void**)&p3h,g_u3h);   cudaGetSymbolAddress((void**)&p3l,g_u3l);

    cudaFuncSetAttribute(conv_hmma<2,4>, cudaFuncAttributeMaxDynamicSharedMemorySize, CONV_SMEM);
    cudaFuncSetAttribute(conv_hmma<1,4>, cudaFuncAttributeMaxDynamicSharedMemorySize, CONV_SMEM);
    cudaFuncSetAttribute(conv_hmma<1,2>, cudaFuncAttributeMaxDynamicSharedMemorySize, CONV_SMEM);
    cudaFuncSetAttribute(conv_hmma<1,1>, cudaFuncAttributeMaxDynamicSharedMemorySize, CONV_SMEM);

    // launches 1-3 (profiled slot 4 = conv2)
    { int t=1152*2208; pack_w_k<<<dim3((t+255)/256,9),256>>>(c2w, w2h, w2l, 1104, 2208, 2208, 19872, t); }
    { int t=BATCH*2208*320; pack_x_k<<<(t+255)/256,256>>>(x32, px32, t); }
    zero6_k<<<(BATCH*552*1280+255)/256,256>>>(xd0, BATCH*1104*320, xd1, BATCH*552*1280,
                                              ll1, BATCH*1280, h1, BATCH*3*1280,
                                              h2, BATCH*3*5120, h3, BATCH*3*20480);

    // 4: conv2 (edge): 2208->1104, 10x32, Mtiles=9, S=4
    conv_hmma<2,4><<<dim3(3, 9*4, BATCH), 256, CONV_SMEM>>>(w2h, w2l, px32, xd0,
        2208, 2208, 1104, 10, 32, 19872, 4, 0, nullptr, nullptr, 0);
    finalize_big<<<(BATCH*1104*320+255)/256,256>>>(xd0, c2b, nullptr, 1104, 320, 0, BATCH*1104*320);

    { int t=640*1504;  pack_w_k<<<dim3((t+255)/256,9),256>>>(u1w, p1h, p1l, 552, 1488, 1504, 13536, t); }
    { int t = BATCH*1488*20*64;
      feat_pack_k<<<(t+255)/256,256>>>(xd0, x16, nullptr, nullptr, cat1, 1104, 384, 20, 64, t); }
    // up1 (reflect): 1488->552, S=2. Bulk: 4 x MT4 (512 rows). Remainder: 1 x MT2 at 512.
    conv_hmma<1,4><<<dim3(10, 4*2, BATCH), 256, CONV_SMEM>>>(p1h, p1l, cat1, xd1,
        1488, 1504, 552, 20, 64, 13536, 2, 0, nullptr, nullptr, 0);
    conv_hmma<1,2><<<dim3(10, 1*2, BATCH), 256, CONV_SMEM>>>(p1h, p1l, cat1, xd1,
        1488, 1504, 552, 20, 64, 13536, 2, 512, nullptr, nullptr, 0);
    finalize_big<<<(BATCH*552*1280+255)/256,256>>>(xd1, u1b, nullptr, 552, 1280, 1, BATCH*552*1280);
    conv_small_part<1,2><<<dim3(10,12,BATCH),128>>>(xd1, wllw, ll1, 552, 12, 20, 64);
    conv_small_part<3,0><<<dim3(10,12,BATCH),128>>>(xd1, w1w, h1, 552, 12, 20, 64);
    finalize_small<<<(BATCH*1280+255)/256,256>>>(ll1, wllb, nullptr, 1, 20, 64, 8.f, BATCH*1280);
    finalize_small<<<(BATCH*3*1280+255)/256,256>>>(h1, w1b, nullptr, 3, 20, 64, 4.f, BATCH*3*1280);
    idwt_k<<<dim3(5,1,BATCH),256>>>(ll1, h1, ll40, 20, 64);
    minmax_k<<<1,1024>>>(ll40, BATCH*40*128, thr);
    mask_k<<<dim3(5,1,BATCH),256>>>(h1, thr, mask1, 20, 64);
    pool_coarse_k<<<dim3(5,1,BATCH),256>>>(mask1, upm1, 20, 64);
    pool_fine_k<<<dim3(20,1,BATCH),256>>>(mask1, cam1, wm1, 20, 64);

    { int t=320*768;   pack_w_k<<<dim3((t+255)/256,9),256>>>(u2w, p2h, p2l, 276, 744, 768, 6912, t); }
    { int t = BATCH*744*40*128;
      feat_pack_k<<<(t+255)/256,256>>>(xd1, x8, upm1, cam1, feat1, 552, 192, 40, 128, t); }
    // up2 (reflect): 744->276, S=1, fused. Bulk: 2 x MT4 (256). Remainder: 1 x MT1 at 256.
    conv_hmma<1,4><<<dim3(40, 2, BATCH), 256, CONV_SMEM>>>(p2h, p2l, feat1, xa,
        744, 768, 276, 40, 128, 6912, 1, 0, u2b, wm1, 1);
    conv_hmma<1,1><<<dim3(40, 1, BATCH), 256, CONV_SMEM>>>(p2h, p2l, feat1, xa,
        744, 768, 276, 40, 128, 6912, 1, 256, u2b, wm1, 1);
    conv_small_part<3,0><<<dim3(40,8,BATCH),128>>>(xa, w2w, h2, 276, 8, 40, 128);
    finalize_small<<<(BATCH*3*5120+255)/256,256>>>(h2, w2b, mask1, 3, 40, 128, 2.f, BATCH*3*5120);
    idwt_k<<<dim3(20,1,BATCH),256>>>(ll40, h2, ll80, 40, 128);
    minmax_k<<<1,1024>>>(ll80, BATCH*80*256, thr);
    mask_k<<<dim3(20,1,BATCH),256>>>(h2, thr, mask2, 40, 128);
    pool_coarse_k<<<dim3(20,1,BATCH),256>>>(mask2, upm2, 40, 128);
    pool_fine_k<<<dim3(80,1,BATCH),256>>>(mask2, cam2, wm2, 40, 128);

    { int t=160*384;   pack_w_k<<<dim3((t+255)/256,9),256>>>(u3w, p3h, p3l, 138, 372, 384, 3456, t); }
    { int t = BATCH*372*80*256;
      feat_pack_k<<<(t+255)/256,256>>>(xa, x4, upm2, cam2, feat0, 276, 96, 80, 256, t); }
    // up3 (reflect): 372->138, S=1, fused. Bulk: 1 x MT4 (128). Remainder: 1 x MT1 at 128.
    conv_hmma<1,4><<<dim3(160, 1, BATCH), 256, CONV_SMEM>>>(p3h, p3l, feat0, xb,
        372, 384, 138, 80, 256, 3456, 1, 0, u3b, wm2, 1);
    conv_hmma<1,1><<<dim3(160, 1, BATCH), 256, CONV_SMEM>>>(p3h, p3l, feat0, xb,
        372, 384, 138, 80, 256, 3456, 1, 128, u3b, wm2, 1);
    conv_small_part<3,0><<<dim3(160,4,BATCH),128>>>(xb, w3w, h3, 138, 4, 80, 256);
    finalize_small<<<(BATCH*3*20480+255)/256,256>>>(h3, w3b, mask2, 3, 80, 256, 1.f, BATCH*3*20480);
    idwt_k<<<dim3(80,1,BATCH),256>>>(ll80, h3, (float*)d_out, 80, 256);
}

// round 14
// speedup vs baseline: 1.0939x; 1.0583x over previous
#include <cuda_runtime.h>
#include <cuda_bf16.h>
#include <math.h>
#include <stdint.h>

#define BATCH 4

__device__ __forceinline__ uint32_t smem_u32(const void* p){
    uint32_t a; asm("{ .reg .u64 t; cvta.to.shared.u64 t, %1; cvt.u32.u64 %0, t; }":"=r"(a):"l"(p)); return a;
}
__device__ __forceinline__ void ldsm4(uint32_t& r0, uint32_t& r1, uint32_t& r2, uint32_t& r3, uint32_t a){
    asm volatile("ldmatrix.sync.aligned.m8n8.x4.shared.b16 {%0,%1,%2,%3}, [%4];"
        :"=r"(r0),"=r"(r1),"=r"(r2),"=r"(r3):"r"(a));
}
__device__ __forceinline__ void mma16816(float* c, const uint32_t* a, const uint32_t* b){
    asm volatile("mma.sync.aligned.m16n8k16.row.col.f32.bf16.bf16.f32 "
        "{%0,%1,%2,%3}, {%4,%5,%6,%7}, {%8,%9}, {%0,%1,%2,%3};"
        : "+f"(c[0]),"+f"(c[1]),"+f"(c[2]),"+f"(c[3])
        : "r"(a[0]),"r"(a[1]),"r"(a[2]),"r"(a[3]),"r"(b[0]),"r"(b[1]));
}
__device__ __forceinline__ void cpasync16(uint32_t saddr, const void* g){
    asm volatile("cp.async.cg.shared.global [%0], [%1], 16;"::"r"(saddr),"l"(g));
}
__device__ __forceinline__ void cpcommit(){ asm volatile("cp.async.commit_group;"); }
__device__ __forceinline__ void cpwait0(){ asm volatile("cp.async.wait_group 0;"); }
__device__ __forceinline__ uint32_t packf(float v){
    __nv_bfloat16 h = __float2bfloat16(v);
    __nv_bfloat16 l = __float2bfloat16(v - __bfloat162float(h));
    return (uint32_t)*(unsigned short*)&h | ((uint32_t)*(unsigned short*)&l << 16);
}

// ---------------- scratch ----------------
__device__ float g_xd0[BATCH*1104*10*32];
__device__ float g_xd1[BATCH*552*20*64];
__device__ float g_ll1[BATCH*20*64];
__device__ float g_h1[BATCH*3*20*64];
__device__ float g_ll40[BATCH*40*128];
__device__ float g_mask1[BATCH*20*64];
__device__ float g_upm1[BATCH*20*64];
__device__ float g_cam1[BATCH*40*128];
__device__ float g_wm1[BATCH*40*128];
__device__ float g_xa[BATCH*276*40*128];
__device__ float g_h2[BATCH*3*40*128];
__device__ float g_ll80[BATCH*80*256];
__device__ float g_mask2[BATCH*40*128];
__device__ float g_upm2[BATCH*40*128];
__device__ float g_cam2[BATCH*80*256];
__device__ float g_wm2[BATCH*80*256];
__device__ float g_xb[BATCH*138*80*256];
__device__ float g_h3[BATCH*3*80*256];
__device__ float g_thr[1];
// packed u32 (bf16 hi | lo<<16) conv inputs
__device__ __align__(16) uint32_t g_px32[BATCH*2208*10*32];
__device__ __align__(16) uint32_t g_cat1[BATCH*1488*20*64];
__device__ __align__(16) uint32_t g_feat1[BATCH*744*40*128];
__device__ __align__(16) uint32_t g_feat0[BATCH*372*80*256];
// packed weights (hi/lo planes), K reordered as t*ICpad+ic
__device__ __align__(16) __nv_bfloat16 g_w2h[1152*19872];
__device__ __align__(16) __nv_bfloat16 g_w2l[1152*19872];
__device__ __align__(16) __nv_bfloat16 g_u1h[640*13536];
__device__ __align__(16) __nv_bfloat16 g_u1l[640*13536];
__device__ __align__(16) __nv_bfloat16 g_u2h[384*6912];
__device__ __align__(16) __nv_bfloat16 g_u2l[384*6912];
__device__ __align__(16) __nv_bfloat16 g_u3h[256*3456];
__device__ __align__(16) __nv_bfloat16 g_u3l[256*3456];

// ---------------- weight pack: w[oc, ic*9+t] -> planes[ocpad, t*ICpad+ic] ----------------
__global__ void pack_w_k(const float* __restrict__ w, __nv_bfloat16* __restrict__ hi,
                         __nv_bfloat16* __restrict__ lo, int OC, int IC, int ICpad, int Kpad, int totRC)
{
    int i = blockIdx.x*256 + threadIdx.x;
    if (i >= totRC) return;
    int t = blockIdx.y;
    int r = i / ICpad, ic = i - r*ICpad;
    float v = (r < OC && ic < IC) ? w[(size_t)r*IC*9 + ic*9 + t] : 0.f;
    __nv_bfloat16 h = __float2bfloat16(v);
    size_t o = (size_t)r*Kpad + t*ICpad + ic;
    hi[o] = h;
    lo[o] = __float2bfloat16(v - __bfloat162float(h));
}

// ---------------- input pack ----------------
__global__ void pack_x_k(const float* __restrict__ x, uint32_t* __restrict__ o, int total)
{
    int i = blockIdx.x*256 + threadIdx.x;
    if (i < total) o[i] = packf(x[i]);
}

// ---------------- zero accumulators ----------------
__global__ void zero6_k(float* a,int na, float* b,int nb, float* c,int nc,
                        float* d,int nd, float* e,int ne, float* f,int nf)
{
    int i = blockIdx.x*256 + threadIdx.x;
    if (i < na) a[i] = 0.f;
    if (i < nb) b[i] = 0.f;
    if (i < nc) c[i] = 0.f;
    if (i < nd) d[i] = 0.f;
    if (i < ne) e[i] = 0.f;
    if (i < nf) f[i] = 0.f;
}

// ---------------- feat build + pack ----------------
__global__ void feat_pack_k(const float* __restrict__ xc, const float* __restrict__ skip,
                            const float* __restrict__ upm, const float* __restrict__ cam,
                            uint32_t* __restrict__ out, int C1, int C2, int Hf, int Wf, int total)
{
    int idx = blockIdx.x*256 + threadIdx.x;
    if (idx >= total) return;
    int Wc = Wf >> 1, Hc = Hf >> 1;
    int x = idx % Wf; int t = idx / Wf;
    int y = t % Hf;  t /= Hf;
    int c = t % (C1+C2); int b = t / (C1+C2);
    float v;
    if (c < C1) {
        v = xc[((size_t)b*C1 + c)*Hc*Wc + (size_t)(y>>1)*Wc + (x>>1)];
        if (upm) v *= upm[(size_t)b*Hc*Wc + (size_t)(y>>1)*Wc + (x>>1)];
    } else {
        v = skip[((size_t)b*C2 + (c-C1))*Hf*Wf + (size_t)y*Wf + x];
    }
    if (cam) v *= cam[(size_t)b*Hf*Wf + (size_t)y*Wf + x];
    out[idx] = packf(v);
}

// ---------------- HMMA implicit-GEMM conv: K-chunk 32, double-buffered, 2 CTA/SM, staged gather ----------------
#define ROWB 80
#define S_AH 0
#define S_AL 10240
#define S_BH 20480
#define S_BL 30720
#define BUFSZ 40960
#define CONV_SMEM (2*BUFSZ)

template<int PAD, int MT>  // PAD: 1 reflect, 2 edge. M-tile = 32*MT rows.
__global__ __launch_bounds__(256, 2)
void conv_hmma(const __nv_bfloat16* __restrict__ Ah, const __nv_bfloat16* __restrict__ Al,
               const uint32_t* __restrict__ pin, float* __restrict__ out,
               int IC, int ICpad, int OC, int H, int W, int Kpad, int S,
               const float* __restrict__ bias, const float* __restrict__ mask, int leaky)
{
    extern __shared__ __align__(16) unsigned char sm[];
    const uint32_t sb = smem_u32(sm);
    const int tid = threadIdx.x, wid = tid >> 5, lane = tid & 31;
    const int HW = H * W;
    const int n0 = blockIdx.x * 128;
    const int Mtiles = gridDim.y / S;
    const int mt_id = blockIdx.y % Mtiles, ks = blockIdx.y / Mtiles;
    const int m0 = mt_id * (32*MT);
    const int b = blockIdx.z;

    const int chunks = Kpad >> 5;
    const int cseg = (chunks + S - 1) / S;
    const int c0 = ks * cseg, c1 = min(chunks, c0 + cseg);

    const uint32_t* inb = pin + (size_t)b * IC * HW;
    const int wm = (wid >> 2) * (16*MT), wn = (wid & 3) * 32;

    float acc[MT][4][4];
    #pragma unroll
    for (int i=0;i<MT;i++) for (int j=0;j<4;j++) for (int k=0;k<4;k++) acc[i][j][k]=0.f;

    const int mloc = tid >> 1, kh = tid & 1;
    const int nglob = n0 + mloc;
    const bool okpix = (nglob < HW);
    const int py = okpix ? nglob / W : 0;
    const int px_ = okpix ? nglob - py*W : 0;

    int kthr = (c0 << 5) + kh*16;
    int tap = kthr / ICpad;
    int icr = kthr - tap*ICpad;

    uint32_t bv[16];   // staged B values; LDG latency overlapped with compute

    auto issueA = [&](int c, int bo){
        const int kc = c << 5;
        #pragma unroll
        for (int i = 0; i < MT; ++i) {
            int flat = i*256 + tid;
            int fo = flat * 16;
            int plane = fo / (MT*2048);
            int rem = fo - plane*(MT*2048);
            int row = rem >> 6, col = rem & 63;
            const __nv_bfloat16* src = (plane ? Al : Ah) + (size_t)(m0+row)*Kpad + kc + (col>>1);
            cpasync16(sb + bo + (plane ? S_AL : S_AH) + row*ROWB + col, src);
        }
        cpcommit();
    };
    auto gatherRegs = [&](){
        int t3 = (tap*11) >> 5;
        int dy = t3 - 1, dx = tap - t3*3 - 1;
        int yy = py + dy, xx = px_ + dx;
        if (PAD == 1) {
            yy = yy<0 ? -yy : (yy>=H ? 2*H-2-yy : yy);
            xx = xx<0 ? -xx : (xx>=W ? 2*W-2-xx : xx);
        } else {
            yy = min(max(yy,0),H-1); xx = min(max(xx,0),W-1);
        }
        const uint32_t* p = inb + (size_t)icr*HW + yy*W + xx;
        #pragma unroll
        for (int e = 0; e < 16; ++e)
            bv[e] = (okpix && (icr + e) < IC) ? __ldg(p + (size_t)e*HW) : 0u;
        icr += 32;
        if (icr >= ICpad) { icr -= ICpad; ++tap; }
    };
    auto stsB = [&](int bo){
        int d = bo + mloc*ROWB + kh*32;
        #pragma unroll
        for (int g8 = 0; g8 < 2; ++g8) {
            uint32_t* v = bv + g8*8;
            uint32_t hp0 = __byte_perm(v[0],v[1],0x5410), hp1 = __byte_perm(v[2],v[3],0x5410);
            uint32_t hp2 = __byte_perm(v[4],v[5],0x5410), hp3 = __byte_perm(v[6],v[7],0x5410);
            uint32_t lp0 = __byte_perm(v[0],v[1],0x7632), lp1 = __byte_perm(v[2],v[3],0x7632);
            uint32_t lp2 = __byte_perm(v[4],v[5],0x7632), lp3 = __byte_perm(v[6],v[7],0x7632);
            *(uint4*)(sm + d + S_BH + g8*16) = make_uint4(hp0,hp1,hp2,hp3);
            *(uint4*)(sm + d + S_BL + g8*16) = make_uint4(lp0,lp1,lp2,lp3);
        }
    };

    issueA(c0, 0);
    gatherRegs();

    for (int c = c0; c < c1; ++c) {
        const int bo = ((c - c0) & 1) * BUFSZ;
        const int bn = BUFSZ - bo;
        cpwait0();
        stsB(bo);
        __syncthreads();
        if (c + 1 < c1) {
            issueA(c + 1, bn);
            gatherRegs();
        }
        #pragma unroll
        for (int kk = 0; kk < 2; ++kk) {
            uint32_t bh[4][2], bl[4][2];
            #pragma unroll
            for (int nt2 = 0; nt2 < 2; ++nt2) {
                int g = lane >> 3;
                int brow = wn + nt2*16 + (lane & 7) + ((g & 2) ? 8 : 0);
                uint32_t baddr = sb + bo + brow*ROWB + kk*32 + ((g & 1) ? 16 : 0);
                ldsm4(bh[nt2*2][0], bh[nt2*2][1], bh[nt2*2+1][0], bh[nt2*2+1][1], baddr + S_BH);
                ldsm4(bl[nt2*2][0], bl[nt2*2][1], bl[nt2*2+1][0], bl[nt2*2+1][1], baddr + S_BL);
            }
            #pragma unroll
            for (int mt = 0; mt < MT; ++mt) {
                int arow = wm + mt*16 + (lane & 15);
                uint32_t aaddr = sb + bo + arow*ROWB + kk*32 + ((lane >> 4) ? 16 : 0);
                uint32_t ah[4], al[4];
                ldsm4(ah[0], ah[1], ah[2], ah[3], aaddr + S_AH);
                ldsm4(al[0], al[1], al[2], al[3], aaddr + S_AL);
                #pragma unroll
                for (int nt = 0; nt < 4; ++nt) {
                    mma16816(acc[mt][nt], ah, bh[nt]);
                    mma16816(acc[mt][nt], ah, bl[nt]);
                    mma16816(acc[mt][nt], al, bh[nt]);
                }
            }
        }
    }

    // ---- epilogue ----
    float* ob = out + (size_t)b * OC * HW;
    const float* mb = mask ? mask + (size_t)b*HW : nullptr;
    const bool direct = (S == 1);
    #pragma unroll
    for (int mt = 0; mt < MT; ++mt) {
        #pragma unroll
        for (int nt = 0; nt < 4; ++nt) {
            #pragma unroll
            for (int cr = 0; cr < 4; ++cr) {
                int r = wm + mt*16 + (lane >> 2) + ((cr >= 2) ? 8 : 0);
                int col = wn + nt*8 + (lane & 3)*2 + (cr & 1);
                int oc = m0 + r, px = n0 + col;
                if (oc < OC && px < HW) {
                    float v = acc[mt][nt][cr];
                    if (direct) {
                        if (bias) v += bias[oc];
                        if (leaky) v = v > 0.f ? v : 0.2f*v;
                        if (mb) v *= mb[px];
                        ob[(size_t)oc*HW + px] = v;
                    } else {
                        atomicAdd(ob + (size_t)oc*HW + px, v);
                    }
                }
            }
        }
    }
}

// ---------------- finalize big ----------------
__global__ void finalize_big(float* __restrict__ buf, const float* __restrict__ bias,
                             const float* __restrict__ mask, int C, int HW, int leaky, int total)
{
    int i = blockIdx.x*256 + threadIdx.x;
    if (i >= total) return;
    int p = i % HW, t = i / HW, c = t % C, b = t / C;
    float v = buf[i] + bias[c];
    if (leaky) v = v > 0.f ? v : 0.2f*v;
    if (mask) v *= mask[(size_t)b*HW + p];
    buf[i] = v;
}

// ---------------- small conv partial ----------------
template<int NOUT, int PAD>
__global__ void conv_small_part(const float* __restrict__ in, const float* __restrict__ wgt,
                                float* __restrict__ acc, int IC, int nsp, int H, int W)
{
    int b = blockIdx.z, sp = blockIdx.y;
    int HW = H*W;
    int p = blockIdx.x*128 + threadIdx.x;
    if (p >= HW) return;
    int y = p / W, x = p - y*W;
    int icPer = (IC + nsp - 1)/nsp, ic0 = sp*icPer, ic1 = min(IC, ic0+icPer);
    float a[NOUT];
    #pragma unroll
    for (int j = 0; j < NOUT; ++j) a[j] = 0.f;
    const float* inb = in + (size_t)b*IC*HW;
    for (int ic = ic0; ic < ic1; ++ic) {
        const float* ip = inb + (size_t)ic*HW;
        const float* wp = wgt + (size_t)ic*9;
        #pragma unroll
        for (int t = 0; t < 9; ++t) {
            int yy = y + t/3 - 1, xx = x + t%3 - 1;
            float v;
            if (PAD == 0) v = (yy>=0 && yy<H && xx>=0 && xx<W) ? __ldg(ip + yy*W + xx) : 0.f;
            else { yy = min(max(yy,0),H-1); xx = min(max(xx,0),W-1); v = __ldg(ip + yy*W + xx); }
            #pragma unroll
            for (int j = 0; j < NOUT; ++j)
                a[j] = fmaf(v, __ldg(wp + (size_t)j*IC*9 + t), a[j]);
        }
    }
    #pragma unroll
    for (int j = 0; j < NOUT; ++j)
        atomicAdd(acc + ((size_t)b*NOUT + j)*HW + p, a[j]);
}

__global__ void finalize_small(float* __restrict__ buf, const float* __restrict__ bias,
                               const float* __restrict__ mask, int NOUT, int H, int W,
                               float scale, int total)
{
    int i = blockIdx.x*256 + threadIdx.x;
    if (i >= total) return;
    int HW = H*W;
    int p = i % HW, t = i / HW, c = t % NOUT, b = t / NOUT;
    float v = (buf[i] + bias[c]) * scale;
    if (mask) {
        int y = p / W, x = p - y*W;
        v *= mask[(size_t)b*(HW/4) + (y>>1)*(W>>1) + (x>>1)];
    }
    buf[i] = v;
}

// ---------------- glue ----------------
__global__ void idwt_k(const float* __restrict__ ll, const float* __restrict__ h,
                       float* __restrict__ out, int Hc, int Wc)
{
    int b = blockIdx.z;
    int p = blockIdx.x*256 + threadIdx.x;
    if (p >= Hc*Wc) return;
    int y = p / Wc, x = p - y*Wc;
    float l = ll[(size_t)b*Hc*Wc + p];
    const float* hb = h + (size_t)b*3*Hc*Wc;
    float lh = hb[p], hl = hb[Hc*Wc+p], hh = hb[2*Hc*Wc+p];
    float a = (l+lh)*0.5f, c2 = (l-lh)*0.5f, d2 = (hl+hh)*0.5f, e = (hl-hh)*0.5f;
    float* ob = out + (size_t)b*(2*Hc)*(2*Wc);
    int W2 = 2*Wc;
    ob[(size_t)(2*y)*W2 + 2*x]     = a + d2;
    ob[(size_t)(2*y)*W2 + 2*x+1]   = c2 + e;
    ob[(size_t)(2*y+1)*W2 + 2*x]   = a - d2;
    ob[(size_t)(2*y+1)*W2 + 2*x+1] = c2 - e;
}
__global__ void minmax_k(const float* __restrict__ d, int n, float* __restrict__ thr)
{
    __shared__ float smn[1024], smx[1024];
    int tid = threadIdx.x;
    float mn = 3.4e38f, mx = -3.4e38f;
    for (int i = tid; i < n; i += 1024) { float v = d[i]; mn = fminf(mn,v); mx = fmaxf(mx,v); }
    smn[tid]=mn; smx[tid]=mx; __syncthreads();
    for (int s=512; s>0; s>>=1) {
        if (tid<s){ smn[tid]=fminf(smn[tid],smn[tid+s]); smx[tid]=fmaxf(smx[tid],smx[tid+s]); }
        __syncthreads();
    }
    if (tid==0) thr[0] = (smx[0]-smn[0])*0.1f;
}
__global__ void mask_k(const float* __restrict__ h, const float* __restrict__ thr,
                       float* __restrict__ mask, int Hc, int Wc)
{
    int b = blockIdx.z;
    int p = blockIdx.x*256 + threadIdx.x;
    if (p >= Hc*Wc) return;
    const float* hb = h + (size_t)b*3*Hc*Wc;
    float m = fmaxf(fabsf(hb[p]), fmaxf(fabsf(hb[Hc*Wc+p]), fabsf(hb[2*Hc*Wc+p])));
    mask[(size_t)b*Hc*Wc + p] = (m > thr[0]) ? 1.f : 0.f;
}
__global__ void pool_coarse_k(const float* __restrict__ mask, float* __restrict__ upm, int Hc, int Wc)
{
    int b = blockIdx.z;
    int p = blockIdx.x*256 + threadIdx.x;
    if (p >= Hc*Wc) return;
    int y = p / Wc, x = p - y*Wc;
    const float* mb = mask + (size_t)b*Hc*Wc;
    float r = 0.f;
    for (int dy=-2;dy<=2;dy++){ int yy=y+dy; if (yy<0||yy>=Hc) continue;
      for (int dx=-2;dx<=2;dx++){ int xx=x+dx; if (xx<0||xx>=Wc) continue;
        r = fmaxf(r, mb[yy*Wc+xx]); } }
    upm[(size_t)b*Hc*Wc + p] = (r > 0.f) ? 1.f : 0.f;
}
__global__ void pool_fine_k(const float* __restrict__ mask, float* __restrict__ cam,
                            float* __restrict__ wm, int Hc, int Wc)
{
    int b = blockIdx.z;
    int Hf = 2*Hc, Wf = 2*Wc;
    int p = blockIdx.x*256 + threadIdx.x;
    if (p >= Hf*Wf) return;
    int y = p / Wf, x = p - y*Wf;
    const float* mb = mask + (size_t)b*Hc*Wc;
    float c5 = 0.f, c3 = 0.f;
    for (int dy=-2;dy<=2;dy++){ int fy=y+dy; if (fy<0||fy>=Hf) continue;
      for (int dx=-2;dx<=2;dx++){ int fx=x+dx; if (fx<0||fx>=Wf) continue;
        float v = mb[(fy>>1)*Wc + (fx>>1)];
        c5 = fmaxf(c5, v);
        if (dy>=-1 && dy<=1 && dx>=-1 && dx<=1) c3 = fmaxf(c3, v);
      } }
    cam[(size_t)b*Hf*Wf + p] = (c5 > 0.f) ? 1.f : 0.f;
    wm [(size_t)b*Hf*Wf + p] = (c3 > 0.f) ? 1.f : 0.f;
}

// =======================================================================
extern "C" void kernel_launch(void* const* d_in, const int* in_sizes, int n_in,
                              void* d_out, int out_size)
{
    const float* x32 = (const float*)d_in[0];
    const float* x16 = (const float*)d_in[1];
    const float* x8  = (const float*)d_in[2];
    const float* x4  = (const float*)d_in[3];
    const float* c2w = (const float*)d_in[4];  const float* c2b = (const float*)d_in[5];
    const float* u1w = (const float*)d_in[6];  const float* u1b = (const float*)d_in[7];
    const float* wllw= (const float*)d_in[8];  const float* wllb= (const float*)d_in[9];
    const float* w1w = (const float*)d_in[10]; const float* w1b = (const float*)d_in[11];
    const float* u2w = (const float*)d_in[12]; const float* u2b = (const float*)d_in[13];
    const float* w2w = (const float*)d_in[14]; const float* w2b = (const float*)d_in[15];
    const float* u3w = (const float*)d_in[16]; const float* u3b = (const float*)d_in[17];
    const float* w3w = (const float*)d_in[18]; const float* w3b = (const float*)d_in[19];

    float *xd0,*xd1,*ll1,*h1,*ll40,*mask1,*upm1,*cam1,*wm1;
    float *xa,*h2,*ll80,*mask2,*upm2,*cam2,*wm2,*xb,*h3,*thr;
    uint32_t *px32,*cat1,*feat1,*feat0;
    __nv_bfloat16 *w2h,*w2l,*p1h,*p1l,*p2h,*p2l,*p3h,*p3l;
    cudaGetSymbolAddress((void**)&xd0,g_xd0);   cudaGetSymbolAddress((void**)&xd1,g_xd1);
    cudaGetSymbolAddress((void**)&ll1,g_ll1);   cudaGetSymbolAddress((void**)&h1,g_h1);
    cudaGetSymbolAddress((void**)&ll40,g_ll40); cudaGetSymbolAddress((void**)&mask1,g_mask1);
    cudaGetSymbolAddress((void**)&upm1,g_upm1); cudaGetSymbolAddress((void**)&cam1,g_cam1);
    cudaGetSymbolAddress((void**)&wm1,g_wm1);   cudaGetSymbolAddress((void**)&xa,g_xa);
    cudaGetSymbolAddress((void**)&h2,g_h2);     cudaGetSymbolAddress((void**)&ll80,g_ll80);
    cudaGetSymbolAddress((void**)&mask2,g_mask2); cudaGetSymbolAddress((void**)&upm2,g_upm2);
    cudaGetSymbolAddress((void**)&cam2,g_cam2); cudaGetSymbolAddress((void**)&wm2,g_wm2);
    cudaGetSymbolAddress((void**)&xb,g_xb);     cudaGetSymbolAddress((void**)&h3,g_h3);
    cudaGetSymbolAddress((void**)&thr,g_thr);
    cudaGetSymbolAddress((void**)&px32,g_px32); cudaGetSymbolAddress((void**)&cat1,g_cat1);
    cudaGetSymbolAddress((void**)&feat1,g_feat1); cudaGetSymbolAddress((void**)&feat0,g_feat0);
    cudaGetSymbolAddress((void**)&w2h,g_w2h);   cudaGetSymbolAddress((void**)&w2l,g_w2l);
    cudaGetSymbolAddress((void**)&p1h,g_u1h);   cudaGetSymbolAddress((void**)&p1l,g_u1l);
    cudaGetSymbolAddress((void**)&p2h,g_u2h);   cudaGetSymbolAddress((void**)&p2l,g_u2l);
    cudaGetSymbolAddress((void**)&p3h,g_u3h);   cudaGetSymbolAddress((void**)&p3l,g_u3l);

    cudaFuncSetAttribute(conv_hmma<2,4>, cudaFuncAttributeMaxDynamicSharedMemorySize, CONV_SMEM);
    cudaFuncSetAttribute(conv_hmma<1,4>, cudaFuncAttributeMaxDynamicSharedMemorySize, CONV_SMEM);
    cudaFuncSetAttribute(conv_hmma<1,2>, cudaFuncAttributeMaxDynamicSharedMemorySize, CONV_SMEM);

    // launches 1-3 (profiled slot 4 = conv2)
    { int t=1152*2208; pack_w_k<<<dim3((t+255)/256,9),256>>>(c2w, w2h, w2l, 1104, 2208, 2208, 19872, t); }
    { int t=BATCH*2208*320; pack_x_k<<<(t+255)/256,256>>>(x32, px32, t); }
    zero6_k<<<(BATCH*552*1280+255)/256,256>>>(xd0, BATCH*1104*320, xd1, BATCH*552*1280,
                                              ll1, BATCH*1280, h1, BATCH*3*1280,
                                              h2, BATCH*3*5120, h3, BATCH*3*20480);

    // 4: conv2 (edge): 2208->1104, 10x32, Mtiles=9, S=8 (deep K-split for wave balance)
    conv_hmma<2,4><<<dim3(3, 9*8, BATCH), 256, CONV_SMEM>>>(w2h, w2l, px32, xd0,
        2208, 2208, 1104, 10, 32, 19872, 8, nullptr, nullptr, 0);
    finalize_big<<<(BATCH*1104*320+255)/256,256>>>(xd0, c2b, nullptr, 1104, 320, 0, BATCH*1104*320);

    { int t=640*1504;  pack_w_k<<<dim3((t+255)/256,9),256>>>(u1w, p1h, p1l, 552, 1488, 1504, 13536, t); }
    { int t = BATCH*1488*20*64;
      feat_pack_k<<<(t+255)/256,256>>>(xd0, x16, nullptr, nullptr, cat1, 1104, 384, 20, 64, t); }
    // up1 (reflect): 1488->552, Mtiles=5, S=4 (deep K-split)
    conv_hmma<1,4><<<dim3(10, 5*4, BATCH), 256, CONV_SMEM>>>(p1h, p1l, cat1, xd1,
        1488, 1504, 552, 20, 64, 13536, 4, nullptr, nullptr, 0);
    finalize_big<<<(BATCH*552*1280+255)/256,256>>>(xd1, u1b, nullptr, 552, 1280, 1, BATCH*552*1280);
    conv_small_part<1,2><<<dim3(10,12,BATCH),128>>>(xd1, wllw, ll1, 552, 12, 20, 64);
    conv_small_part<3,0><<<dim3(10,12,BATCH),128>>>(xd1, w1w, h1, 552, 12, 20, 64);
    finalize_small<<<(BATCH*1280+255)/256,256>>>(ll1, wllb, nullptr, 1, 20, 64, 8.f, BATCH*1280);
    finalize_small<<<(BATCH*3*1280+255)/256,256>>>(h1, w1b, nullptr, 3, 20, 64, 4.f, BATCH*3*1280);
    idwt_k<<<dim3(5,1,BATCH),256>>>(ll1, h1, ll40, 20, 64);
    minmax_k<<<1,1024>>>(ll40, BATCH*40*128, thr);
    mask_k<<<dim3(5,1,BATCH),256>>>(h1, thr, mask1, 20, 64);
    pool_coarse_k<<<dim3(5,1,BATCH),256>>>(mask1, upm1, 20, 64);
    pool_fine_k<<<dim3(20,1,BATCH),256>>>(mask1, cam1, wm1, 20, 64);

    { int t=384*768;   pack_w_k<<<dim3((t+255)/256,9),256>>>(u2w, p2h, p2l, 276, 744, 768, 6912, t); }
    { int t = BATCH*744*40*128;
      feat_pack_k<<<(t+255)/256,256>>>(xd1, x8, upm1, cam1, feat1, 552, 192, 40, 128, t); }
    // up2 (reflect): 744->276, Mtiles=3 (MT4), S=1, fused epilogue
    conv_hmma<1,4><<<dim3(40, 3, BATCH), 256, CONV_SMEM>>>(p2h, p2l, feat1, xa,
        744, 768, 276, 40, 128, 6912, 1, u2b, wm1, 1);
    conv_small_part<3,0><<<dim3(40,8,BATCH),128>>>(xa, w2w, h2, 276, 8, 40, 128);
    finalize_small<<<(BATCH*3*5120+255)/256,256>>>(h2, w2b, mask1, 3, 40, 128, 2.f, BATCH*3*5120);
    idwt_k<<<dim3(20,1,BATCH),256>>>(ll40, h2, ll80, 40, 128);
    minmax_k<<<1,1024>>>(ll80, BATCH*80*256, thr);
    mask_k<<<dim3(20,1,BATCH),256>>>(h2, thr, mask2, 40, 128);
    pool_coarse_k<<<dim3(20,1,BATCH),256>>>(mask2, upm2, 40, 128);
    pool_fine_k<<<dim3(80,1,BATCH),256>>>(mask2, cam2, wm2, 40, 128);

    { int t=256*384;   pack_w_k<<<dim3((t+255)/256,9),256>>>(u3w, p3h, p3l, 138, 372, 384, 3456, t); }
    { int t = BATCH*372*80*256;
      feat_pack_k<<<(t+255)/256,256>>>(xa, x4, upm2, cam2, feat0, 276, 96, 80, 256, t); }
    // up3 (reflect): 372->138, M-tile=64 (MT2), Mtiles=3, S=1, fused epilogue
    conv_hmma<1,2><<<dim3(160, 3, BATCH), 256, CONV_SMEM>>>(p3h, p3l, feat0, xb,
        372, 384, 138, 80, 256, 3456, 1, u3b, wm2, 1);
    conv_small_part<3,0><<<dim3(160,4,BATCH),128>>>(xb, w3w, h3, 138, 4, 80, 256);
    finalize_small<<<(BATCH*3*20480+255)/256,256>>>(h3, w3b, mask2, 3, 80, 256, 1.f, BATCH*3*20480);
    idwt_k<<<dim3(80,1,BATCH),256>>>(ll80, h3, (float*)d_out, 80, 256);
}

// round 15
// speedup vs baseline: 1.2048x; 1.1014x over previous
#include <cuda_runtime.h>
#include <cuda_bf16.h>
#include <math.h>
#include <stdint.h>

#define BATCH 4

__device__ __forceinline__ uint32_t smem_u32(const void* p){
    uint32_t a; asm("{ .reg .u64 t; cvta.to.shared.u64 t, %1; cvt.u32.u64 %0, t; }":"=r"(a):"l"(p)); return a;
}
__device__ __forceinline__ void ldsm4(uint32_t& r0, uint32_t& r1, uint32_t& r2, uint32_t& r3, uint32_t a){
    asm volatile("ldmatrix.sync.aligned.m8n8.x4.shared.b16 {%0,%1,%2,%3}, [%4];"
        :"=r"(r0),"=r"(r1),"=r"(r2),"=r"(r3):"r"(a));
}
__device__ __forceinline__ void mma16816(float* c, const uint32_t* a, const uint32_t* b){
    asm volatile("mma.sync.aligned.m16n8k16.row.col.f32.bf16.bf16.f32 "
        "{%0,%1,%2,%3}, {%4,%5,%6,%7}, {%8,%9}, {%0,%1,%2,%3};"
        : "+f"(c[0]),"+f"(c[1]),"+f"(c[2]),"+f"(c[3])
        : "r"(a[0]),"r"(a[1]),"r"(a[2]),"r"(a[3]),"r"(b[0]),"r"(b[1]));
}
__device__ __forceinline__ void cpasync16(uint32_t saddr, const void* g){
    asm volatile("cp.async.cg.shared.global [%0], [%1], 16;"::"r"(saddr),"l"(g));
}
__device__ __forceinline__ void cpcommit(){ asm volatile("cp.async.commit_group;"); }
__device__ __forceinline__ void cpwait0(){ asm volatile("cp.async.wait_group 0;"); }
__device__ __forceinline__ uint32_t packf(float v){
    __nv_bfloat16 h = __float2bfloat16(v);
    __nv_bfloat16 l = __float2bfloat16(v - __bfloat162float(h));
    return (uint32_t)*(unsigned short*)&h | ((uint32_t)*(unsigned short*)&l << 16);
}

// ---------------- scratch ----------------
__device__ float g_xd0[BATCH*1104*10*32];
__device__ float g_xd1[BATCH*552*20*64];
__device__ float g_ll1[BATCH*20*64];
__device__ float g_h1[BATCH*3*20*64];
__device__ float g_ll40[BATCH*40*128];
__device__ float g_mask1[BATCH*20*64];
__device__ float g_upm1[BATCH*20*64];
__device__ float g_cam1[BATCH*40*128];
__device__ float g_wm1[BATCH*40*128];
__device__ float g_xa[BATCH*276*40*128];
__device__ float g_h2[BATCH*3*40*128];
__device__ float g_ll80[BATCH*80*256];
__device__ float g_mask2[BATCH*40*128];
__device__ float g_upm2[BATCH*40*128];
__device__ float g_cam2[BATCH*80*256];
__device__ float g_wm2[BATCH*80*256];
__device__ float g_xb[BATCH*138*80*256];
__device__ float g_h3[BATCH*3*80*256];
__device__ float g_thr[1];
// packed u32 (bf16 hi | lo<<16) conv inputs
__device__ __align__(16) uint32_t g_px32[BATCH*2208*10*32];
__device__ __align__(16) uint32_t g_cat1[BATCH*1488*20*64];
__device__ __align__(16) uint32_t g_feat1[BATCH*744*40*128];
__device__ __align__(16) uint32_t g_feat0[BATCH*372*80*256];
// packed weights (hi/lo planes), K reordered as t*ICpad+ic
__device__ __align__(16) __nv_bfloat16 g_w2h[1152*19872];
__device__ __align__(16) __nv_bfloat16 g_w2l[1152*19872];
__device__ __align__(16) __nv_bfloat16 g_u1h[640*13536];
__device__ __align__(16) __nv_bfloat16 g_u1l[640*13536];
__device__ __align__(16) __nv_bfloat16 g_u2h[384*6912];
__device__ __align__(16) __nv_bfloat16 g_u2l[384*6912];
__device__ __align__(16) __nv_bfloat16 g_u3h[256*3456];
__device__ __align__(16) __nv_bfloat16 g_u3l[256*3456];

// ---------------- weight pack: w[oc, ic*9+t] -> planes[ocpad, t*ICpad+ic] ----------------
__global__ void pack_w_k(const float* __restrict__ w, __nv_bfloat16* __restrict__ hi,
                         __nv_bfloat16* __restrict__ lo, int OC, int IC, int ICpad, int Kpad, int totRC)
{
    int i = blockIdx.x*256 + threadIdx.x;
    if (i >= totRC) return;
    int t = blockIdx.y;
    int r = i / ICpad, ic = i - r*ICpad;
    float v = (r < OC && ic < IC) ? w[(size_t)r*IC*9 + ic*9 + t] : 0.f;
    __nv_bfloat16 h = __float2bfloat16(v);
    size_t o = (size_t)r*Kpad + t*ICpad + ic;
    hi[o] = h;
    lo[o] = __float2bfloat16(v - __bfloat162float(h));
}

// ---------------- input pack ----------------
__global__ void pack_x_k(const float* __restrict__ x, uint32_t* __restrict__ o, int total)
{
    int i = blockIdx.x*256 + threadIdx.x;
    if (i < total) o[i] = packf(x[i]);
}

// ---------------- zero accumulators ----------------
__global__ void zero6_k(float* a,int na, float* b,int nb, float* c,int nc,
                        float* d,int nd, float* e,int ne, float* f,int nf)
{
    int i = blockIdx.x*256 + threadIdx.x;
    if (i < na) a[i] = 0.f;
    if (i < nb) b[i] = 0.f;
    if (i < nc) c[i] = 0.f;
    if (i < nd) d[i] = 0.f;
    if (i < ne) e[i] = 0.f;
    if (i < nf) f[i] = 0.f;
}

// ---------------- feat build + pack ----------------
__global__ void feat_pack_k(const float* __restrict__ xc, const float* __restrict__ skip,
                            const float* __restrict__ upm, const float* __restrict__ cam,
                            uint32_t* __restrict__ out, int C1, int C2, int Hf, int Wf, int total)
{
    int idx = blockIdx.x*256 + threadIdx.x;
    if (idx >= total) return;
    int Wc = Wf >> 1, Hc = Hf >> 1;
    int x = idx % Wf; int t = idx / Wf;
    int y = t % Hf;  t /= Hf;
    int c = t % (C1+C2); int b = t / (C1+C2);
    float v;
    if (c < C1) {
        v = xc[((size_t)b*C1 + c)*Hc*Wc + (size_t)(y>>1)*Wc + (x>>1)];
        if (upm) v *= upm[(size_t)b*Hc*Wc + (size_t)(y>>1)*Wc + (x>>1)];
    } else {
        v = skip[((size_t)b*C2 + (c-C1))*Hf*Wf + (size_t)y*Wf + x];
    }
    if (cam) v *= cam[(size_t)b*Hf*Wf + (size_t)y*Wf + x];
    out[idx] = packf(v);
}

// ---------------- HMMA implicit-GEMM conv: K-chunk 32, double-buffered, 2 CTA/SM, staged gather ----------------
#define ROWB 80
#define S_AH 0
#define S_AL 10240
#define S_BH 20480
#define S_BL 30720
#define BUFSZ 40960
#define CONV_SMEM (2*BUFSZ)

template<int PAD, int MT>  // PAD: 1 reflect, 2 edge. M-tile = 32*MT rows.
__global__ __launch_bounds__(256, 2)
void conv_hmma(const __nv_bfloat16* __restrict__ Ah, const __nv_bfloat16* __restrict__ Al,
               const uint32_t* __restrict__ pin, float* __restrict__ out,
               int IC, int ICpad, int OC, int H, int W, int Kpad, int S,
               const float* __restrict__ bias, const float* __restrict__ mask, int leaky)
{
    extern __shared__ __align__(16) unsigned char sm[];
    const uint32_t sb = smem_u32(sm);
    const int tid = threadIdx.x, wid = tid >> 5, lane = tid & 31;
    const int HW = H * W;
    const int n0 = blockIdx.x * 128;
    const int Mtiles = gridDim.y / S;
    const int mt_id = blockIdx.y % Mtiles, ks = blockIdx.y / Mtiles;
    const int m0 = mt_id * (32*MT);
    const int b = blockIdx.z;

    const int chunks = Kpad >> 5;
    const int cseg = (chunks + S - 1) / S;
    const int c0 = ks * cseg, c1 = min(chunks, c0 + cseg);

    const uint32_t* inb = pin + (size_t)b * IC * HW;
    const int wm = (wid >> 2) * (16*MT), wn = (wid & 3) * 32;

    float acc[MT][4][4];
    #pragma unroll
    for (int i=0;i<MT;i++) for (int j=0;j<4;j++) for (int k=0;k<4;k++) acc[i][j][k]=0.f;

    const int mloc = tid >> 1, kh = tid & 1;
    const int nglob = n0 + mloc;
    const bool okpix = (nglob < HW);
    const int py = okpix ? nglob / W : 0;
    const int px_ = okpix ? nglob - py*W : 0;

    int kthr = (c0 << 5) + kh*16;
    int tap = kthr / ICpad;
    int icr = kthr - tap*ICpad;

    uint32_t bv[16];   // staged B values; LDG latency overlapped with compute

    auto issueA = [&](int c, int bo){
        const int kc = c << 5;
        #pragma unroll
        for (int i = 0; i < MT; ++i) {
            int flat = i*256 + tid;
            int fo = flat * 16;
            int plane = fo / (MT*2048);
            int rem = fo - plane*(MT*2048);
            int row = rem >> 6, col = rem & 63;
            const __nv_bfloat16* src = (plane ? Al : Ah) + (size_t)(m0+row)*Kpad + kc + (col>>1);
            cpasync16(sb + bo + (plane ? S_AL : S_AH) + row*ROWB + col, src);
        }
        cpcommit();
    };
    auto gatherRegs = [&](){
        int t3 = (tap*11) >> 5;
        int dy = t3 - 1, dx = tap - t3*3 - 1;
        int yy = py + dy, xx = px_ + dx;
        if (PAD == 1) {
            yy = yy<0 ? -yy : (yy>=H ? 2*H-2-yy : yy);
            xx = xx<0 ? -xx : (xx>=W ? 2*W-2-xx : xx);
        } else {
            yy = min(max(yy,0),H-1); xx = min(max(xx,0),W-1);
        }
        const uint32_t* p = inb + (size_t)icr*HW + yy*W + xx;
        #pragma unroll
        for (int e = 0; e < 16; ++e)
            bv[e] = (okpix && (icr + e) < IC) ? __ldg(p + (size_t)e*HW) : 0u;
        icr += 32;
        if (icr >= ICpad) { icr -= ICpad; ++tap; }
    };
    auto stsB = [&](int bo){
        int d = bo + mloc*ROWB + kh*32;
        #pragma unroll
        for (int g8 = 0; g8 < 2; ++g8) {
            uint32_t* v = bv + g8*8;
            uint32_t hp0 = __byte_perm(v[0],v[1],0x5410), hp1 = __byte_perm(v[2],v[3],0x5410);
            uint32_t hp2 = __byte_perm(v[4],v[5],0x5410), hp3 = __byte_perm(v[6],v[7],0x5410);
            uint32_t lp0 = __byte_perm(v[0],v[1],0x7632), lp1 = __byte_perm(v[2],v[3],0x7632);
            uint32_t lp2 = __byte_perm(v[4],v[5],0x7632), lp3 = __byte_perm(v[6],v[7],0x7632);
            *(uint4*)(sm + d + S_BH + g8*16) = make_uint4(hp0,hp1,hp2,hp3);
            *(uint4*)(sm + d + S_BL + g8*16) = make_uint4(lp0,lp1,lp2,lp3);
        }
    };

    issueA(c0, 0);
    gatherRegs();

    for (int c = c0; c < c1; ++c) {
        const int bo = ((c - c0) & 1) * BUFSZ;
        const int bn = BUFSZ - bo;
        cpwait0();
        stsB(bo);
        __syncthreads();
        if (c + 1 < c1) {
            issueA(c + 1, bn);
            gatherRegs();
        }
        #pragma unroll
        for (int kk = 0; kk < 2; ++kk) {
            uint32_t bh[4][2], bl[4][2];
            #pragma unroll
            for (int nt2 = 0; nt2 < 2; ++nt2) {
                int g = lane >> 3;
                int brow = wn + nt2*16 + (lane & 7) + ((g & 2) ? 8 : 0);
                uint32_t baddr = sb + bo + brow*ROWB + kk*32 + ((g & 1) ? 16 : 0);
                ldsm4(bh[nt2*2][0], bh[nt2*2][1], bh[nt2*2+1][0], bh[nt2*2+1][1], baddr + S_BH);
                ldsm4(bl[nt2*2][0], bl[nt2*2][1], bl[nt2*2+1][0], bl[nt2*2+1][1], baddr + S_BL);
            }
            #pragma unroll
            for (int mt = 0; mt < MT; ++mt) {
                int arow = wm + mt*16 + (lane & 15);
                uint32_t aaddr = sb + bo + arow*ROWB + kk*32 + ((lane >> 4) ? 16 : 0);
                uint32_t ah[4], al[4];
                ldsm4(ah[0], ah[1], ah[2], ah[3], aaddr + S_AH);
                ldsm4(al[0], al[1], al[2], al[3], aaddr + S_AL);
                #pragma unroll
                for (int nt = 0; nt < 4; ++nt) {
                    mma16816(acc[mt][nt], ah, bh[nt]);
                    mma16816(acc[mt][nt], ah, bl[nt]);
                    mma16816(acc[mt][nt], al, bh[nt]);
                }
            }
        }
    }

    // ---- epilogue ----
    float* ob = out + (size_t)b * OC * HW;
    const float* mb = mask ? mask + (size_t)b*HW : nullptr;
    const bool direct = (S == 1);
    #pragma unroll
    for (int mt = 0; mt < MT; ++mt) {
        #pragma unroll
        for (int nt = 0; nt < 4; ++nt) {
            #pragma unroll
            for (int cr = 0; cr < 4; ++cr) {
                int r = wm + mt*16 + (lane >> 2) + ((cr >= 2) ? 8 : 0);
                int col = wn + nt*8 + (lane & 3)*2 + (cr & 1);
                int oc = m0 + r, px = n0 + col;
                if (oc < OC && px < HW) {
                    float v = acc[mt][nt][cr];
                    if (direct) {
                        if (bias) v += bias[oc];
                        if (leaky) v = v > 0.f ? v : 0.2f*v;
                        if (mb) v *= mb[px];
                        ob[(size_t)oc*HW + px] = v;
                    } else {
                        atomicAdd(ob + (size_t)oc*HW + px, v);
                    }
                }
            }
        }
    }
}

// ---------------- finalize big ----------------
__global__ void finalize_big(float* __restrict__ buf, const float* __restrict__ bias,
                             const float* __restrict__ mask, int C, int HW, int leaky, int total)
{
    int i = blockIdx.x*256 + threadIdx.x;
    if (i >= total) return;
    int p = i % HW, t = i / HW, c = t % C, b = t / C;
    float v = buf[i] + bias[c];
    if (leaky) v = v > 0.f ? v : 0.2f*v;
    if (mask) v *= mask[(size_t)b*HW + p];
    buf[i] = v;
}

// ---------------- small conv partial ----------------
template<int NOUT, int PAD>
__global__ void conv_small_part(const float* __restrict__ in, const float* __restrict__ wgt,
                                float* __restrict__ acc, int IC, int nsp, int H, int W)
{
    int b = blockIdx.z, sp = blockIdx.y;
    int HW = H*W;
    int p = blockIdx.x*128 + threadIdx.x;
    if (p >= HW) return;
    int y = p / W, x = p - y*W;
    int icPer = (IC + nsp - 1)/nsp, ic0 = sp*icPer, ic1 = min(IC, ic0+icPer);
    float a[NOUT];
    #pragma unroll
    for (int j = 0; j < NOUT; ++j) a[j] = 0.f;
    const float* inb = in + (size_t)b*IC*HW;
    for (int ic = ic0; ic < ic1; ++ic) {
        const float* ip = inb + (size_t)ic*HW;
        const float* wp = wgt + (size_t)ic*9;
        #pragma unroll
        for (int t = 0; t < 9; ++t) {
            int yy = y + t/3 - 1, xx = x + t%3 - 1;
            float v;
            if (PAD == 0) v = (yy>=0 && yy<H && xx>=0 && xx<W) ? __ldg(ip + yy*W + xx) : 0.f;
            else { yy = min(max(yy,0),H-1); xx = min(max(xx,0),W-1); v = __ldg(ip + yy*W + xx); }
            #pragma unroll
            for (int j = 0; j < NOUT; ++j)
                a[j] = fmaf(v, __ldg(wp + (size_t)j*IC*9 + t), a[j]);
        }
    }
    #pragma unroll
    for (int j = 0; j < NOUT; ++j)
        atomicAdd(acc + ((size_t)b*NOUT + j)*HW + p, a[j]);
}

__global__ void finalize_small(float* __restrict__ buf, const float* __restrict__ bias,
                               const float* __restrict__ mask, int NOUT, int H, int W,
                               float scale, int total)
{
    int i = blockIdx.x*256 + threadIdx.x;
    if (i >= total) return;
    int HW = H*W;
    int p = i % HW, t = i / HW, c = t % NOUT, b = t / NOUT;
    float v = (buf[i] + bias[c]) * scale;
    if (mask) {
        int y = p / W, x = p - y*W;
        v *= mask[(size_t)b*(HW/4) + (y>>1)*(W>>1) + (x>>1)];
    }
    buf[i] = v;
}

// ---------------- glue ----------------
__global__ void idwt_k(const float* __restrict__ ll, const float* __restrict__ h,
                       float* __restrict__ out, int Hc, int Wc)
{
    int b = blockIdx.z;
    int p = blockIdx.x*256 + threadIdx.x;
    if (p >= Hc*Wc) return;
    int y = p / Wc, x = p - y*Wc;
    float l = ll[(size_t)b*Hc*Wc + p];
    const float* hb = h + (size_t)b*3*Hc*Wc;
    float lh = hb[p], hl = hb[Hc*Wc+p], hh = hb[2*Hc*Wc+p];
    float a = (l+lh)*0.5f, c2 = (l-lh)*0.5f, d2 = (hl+hh)*0.5f, e = (hl-hh)*0.5f;
    float* ob = out + (size_t)b*(2*Hc)*(2*Wc);
    int W2 = 2*Wc;
    ob[(size_t)(2*y)*W2 + 2*x]     = a + d2;
    ob[(size_t)(2*y)*W2 + 2*x+1]   = c2 + e;
    ob[(size_t)(2*y+1)*W2 + 2*x]   = a - d2;
    ob[(size_t)(2*y+1)*W2 + 2*x+1] = c2 - e;
}
__global__ void minmax_k(const float* __restrict__ d, int n, float* __restrict__ thr)
{
    __shared__ float smn[1024], smx[1024];
    int tid = threadIdx.x;
    float mn = 3.4e38f, mx = -3.4e38f;
    for (int i = tid; i < n; i += 1024) { float v = d[i]; mn = fminf(mn,v); mx = fmaxf(mx,v); }
    smn[tid]=mn; smx[tid]=mx; __syncthreads();
    for (int s=512; s>0; s>>=1) {
        if (tid<s){ smn[tid]=fminf(smn[tid],smn[tid+s]); smx[tid]=fmaxf(smx[tid],smx[tid+s]); }
        __syncthreads();
    }
    if (tid==0) thr[0] = (smx[0]-smn[0])*0.1f;
}
__global__ void mask_k(const float* __restrict__ h, const float* __restrict__ thr,
                       float* __restrict__ mask, int Hc, int Wc)
{
    int b = blockIdx.z;
    int p = blockIdx.x*256 + threadIdx.x;
    if (p >= Hc*Wc) return;
    const float* hb = h + (size_t)b*3*Hc*Wc;
    float m = fmaxf(fabsf(hb[p]), fmaxf(fabsf(hb[Hc*Wc+p]), fabsf(hb[2*Hc*Wc+p])));
    mask[(size_t)b*Hc*Wc + p] = (m > thr[0]) ? 1.f : 0.f;
}
__global__ void pool_coarse_k(const float* __restrict__ mask, float* __restrict__ upm, int Hc, int Wc)
{
    int b = blockIdx.z;
    int p = blockIdx.x*256 + threadIdx.x;
    if (p >= Hc*Wc) return;
    int y = p / Wc, x = p - y*Wc;
    const float* mb = mask + (size_t)b*Hc*Wc;
    float r = 0.f;
    for (int dy=-2;dy<=2;dy++){ int yy=y+dy; if (yy<0||yy>=Hc) continue;
      for (int dx=-2;dx<=2;dx++){ int xx=x+dx; if (xx<0||xx>=Wc) continue;
        r = fmaxf(r, mb[yy*Wc+xx]); } }
    upm[(size_t)b*Hc*Wc + p] = (r > 0.f) ? 1.f : 0.f;
}
__global__ void pool_fine_k(const float* __restrict__ mask, float* __restrict__ cam,
                            float* __restrict__ wm, int Hc, int Wc)
{
    int b = blockIdx.z;
    int Hf = 2*Hc, Wf = 2*Wc;
    int p = blockIdx.x*256 + threadIdx.x;
    if (p >= Hf*Wf) return;
    int y = p / Wf, x = p - y*Wf;
    const float* mb = mask + (size_t)b*Hc*Wc;
    float c5 = 0.f, c3 = 0.f;
    for (int dy=-2;dy<=2;dy++){ int fy=y+dy; if (fy<0||fy>=Hf) continue;
      for (int dx=-2;dx<=2;dx++){ int fx=x+dx; if (fx<0||fx>=Wf) continue;
        float v = mb[(fy>>1)*Wc + (fx>>1)];
        c5 = fmaxf(c5, v);
        if (dy>=-1 && dy<=1 && dx>=-1 && dx<=1) c3 = fmaxf(c3, v);
      } }
    cam[(size_t)b*Hf*Wf + p] = (c5 > 0.f) ? 1.f : 0.f;
    wm [(size_t)b*Hf*Wf + p] = (c3 > 0.f) ? 1.f : 0.f;
}

// =======================================================================
extern "C" void kernel_launch(void* const* d_in, const int* in_sizes, int n_in,
                              void* d_out, int out_size)
{
    const float* x32 = (const float*)d_in[0];
    const float* x16 = (const float*)d_in[1];
    const float* x8  = (const float*)d_in[2];
    const float* x4  = (const float*)d_in[3];
    const float* c2w = (const float*)d_in[4];  const float* c2b = (const float*)d_in[5];
    const float* u1w = (const float*)d_in[6];  const float* u1b = (const float*)d_in[7];
    const float* wllw= (const float*)d_in[8];  const float* wllb= (const float*)d_in[9];
    const float* w1w = (const float*)d_in[10]; const float* w1b = (const float*)d_in[11];
    const float* u2w = (const float*)d_in[12]; const float* u2b = (const float*)d_in[13];
    const float* w2w = (const float*)d_in[14]; const float* w2b = (const float*)d_in[15];
    const float* u3w = (const float*)d_in[16]; const float* u3b = (const float*)d_in[17];
    const float* w3w = (const float*)d_in[18]; const float* w3b = (const float*)d_in[19];

    float *xd0,*xd1,*ll1,*h1,*ll40,*mask1,*upm1,*cam1,*wm1;
    float *xa,*h2,*ll80,*mask2,*upm2,*cam2,*wm2,*xb,*h3,*thr;
    uint32_t *px32,*cat1,*feat1,*feat0;
    __nv_bfloat16 *w2h,*w2l,*p1h,*p1l,*p2h,*p2l,*p3h,*p3l;
    cudaGetSymbolAddress((void**)&xd0,g_xd0);   cudaGetSymbolAddress((void**)&xd1,g_xd1);
    cudaGetSymbolAddress((void**)&ll1,g_ll1);   cudaGetSymbolAddress((void**)&h1,g_h1);
    cudaGetSymbolAddress((void**)&ll40,g_ll40); cudaGetSymbolAddress((void**)&mask1,g_mask1);
    cudaGetSymbolAddress((void**)&upm1,g_upm1); cudaGetSymbolAddress((void**)&cam1,g_cam1);
    cudaGetSymbolAddress((void**)&wm1,g_wm1);   cudaGetSymbolAddress((void**)&xa,g_xa);
    cudaGetSymbolAddress((void**)&h2,g_h2);     cudaGetSymbolAddress((void**)&ll80,g_ll80);
    cudaGetSymbolAddress((void**)&mask2,g_mask2); cudaGetSymbolAddress((void**)&upm2,g_upm2);
    cudaGetSymbolAddress((void**)&cam2,g_cam2); cudaGetSymbolAddress((void**)&wm2,g_wm2);
    cudaGetSymbolAddress((void**)&xb,g_xb);     cudaGetSymbolAddress((void**)&h3,g_h3);
    cudaGetSymbolAddress((void**)&thr,g_thr);
    cudaGetSymbolAddress((void**)&px32,g_px32); cudaGetSymbolAddress((void**)&cat1,g_cat1);
    cudaGetSymbolAddress((void**)&feat1,g_feat1); cudaGetSymbolAddress((void**)&feat0,g_feat0);
    cudaGetSymbolAddress((void**)&w2h,g_w2h);   cudaGetSymbolAddress((void**)&w2l,g_w2l);
    cudaGetSymbolAddress((void**)&p1h,g_u1h);   cudaGetSymbolAddress((void**)&p1l,g_u1l);
    cudaGetSymbolAddress((void**)&p2h,g_u2h);   cudaGetSymbolAddress((void**)&p2l,g_u2l);
    cudaGetSymbolAddress((void**)&p3h,g_u3h);   cudaGetSymbolAddress((void**)&p3l,g_u3l);

    cudaFuncSetAttribute(conv_hmma<2,4>, cudaFuncAttributeMaxDynamicSharedMemorySize, CONV_SMEM);
    cudaFuncSetAttribute(conv_hmma<1,3>, cudaFuncAttributeMaxDynamicSharedMemorySize, CONV_SMEM);

    // launches 1-3 (profiled slot 4 = conv2)
    { int t=1152*2208; pack_w_k<<<dim3((t+255)/256,9),256>>>(c2w, w2h, w2l, 1104, 2208, 2208, 19872, t); }
    { int t=BATCH*2208*320; pack_x_k<<<(t+255)/256,256>>>(x32, px32, t); }
    zero6_k<<<(BATCH*552*1280+255)/256,256>>>(xd0, BATCH*1104*320, xd1, BATCH*552*1280,
                                              ll1, BATCH*1280, h1, BATCH*3*1280,
                                              h2, BATCH*3*5120, h3, BATCH*3*20480);

    // 4: conv2 (edge): 2208->1104, 10x32, MT4 Mtiles=9, S=8
    conv_hmma<2,4><<<dim3(3, 9*8, BATCH), 256, CONV_SMEM>>>(w2h, w2l, px32, xd0,
        2208, 2208, 1104, 10, 32, 19872, 8, nullptr, nullptr, 0);
    finalize_big<<<(BATCH*1104*320+255)/256,256>>>(xd0, c2b, nullptr, 1104, 320, 0, BATCH*1104*320);

    { int t=640*1504;  pack_w_k<<<dim3((t+255)/256,9),256>>>(u1w, p1h, p1l, 552, 1488, 1504, 13536, t); }
    { int t = BATCH*1488*20*64;
      feat_pack_k<<<(t+255)/256,256>>>(xd0, x16, nullptr, nullptr, cat1, 1104, 384, 20, 64, t); }
    // up1 (reflect): 1488->552, MT3 Mtiles=6 (576 rows), S=4
    conv_hmma<1,3><<<dim3(10, 6*4, BATCH), 256, CONV_SMEM>>>(p1h, p1l, cat1, xd1,
        1488, 1504, 552, 20, 64, 13536, 4, nullptr, nullptr, 0);
    finalize_big<<<(BATCH*552*1280+255)/256,256>>>(xd1, u1b, nullptr, 552, 1280, 1, BATCH*552*1280);
    conv_small_part<1,2><<<dim3(10,12,BATCH),128>>>(xd1, wllw, ll1, 552, 12, 20, 64);
    conv_small_part<3,0><<<dim3(10,12,BATCH),128>>>(xd1, w1w, h1, 552, 12, 20, 64);
    finalize_small<<<(BATCH*1280+255)/256,256>>>(ll1, wllb, nullptr, 1, 20, 64, 8.f, BATCH*1280);
    finalize_small<<<(BATCH*3*1280+255)/256,256>>>(h1, w1b, nullptr, 3, 20, 64, 4.f, BATCH*3*1280);
    idwt_k<<<dim3(5,1,BATCH),256>>>(ll1, h1, ll40, 20, 64);
    minmax_k<<<1,1024>>>(ll40, BATCH*40*128, thr);
    mask_k<<<dim3(5,1,BATCH),256>>>(h1, thr, mask1, 20, 64);
    pool_coarse_k<<<dim3(5,1,BATCH),256>>>(mask1, upm1, 20, 64);
    pool_fine_k<<<dim3(20,1,BATCH),256>>>(mask1, cam1, wm1, 20, 64);

    { int t=384*768;   pack_w_k<<<dim3((t+255)/256,9),256>>>(u2w, p2h, p2l, 276, 744, 768, 6912, t); }
    { int t = BATCH*744*40*128;
      feat_pack_k<<<(t+255)/256,256>>>(xd1, x8, upm1, cam1, feat1, 552, 192, 40, 128, t); }
    // up2 (reflect): 744->276, MT3 Mtiles=3 (288 rows), S=1, fused epilogue
    conv_hmma<1,3><<<dim3(40, 3, BATCH), 256, CONV_SMEM>>>(p2h, p2l, feat1, xa,
        744, 768, 276, 40, 128, 6912, 1, u2b, wm1, 1);
    conv_small_part<3,0><<<dim3(40,8,BATCH),128>>>(xa, w2w, h2, 276, 8, 40, 128);
    finalize_small<<<(BATCH*3*5120+255)/256,256>>>(h2, w2b, mask1, 3, 40, 128, 2.f, BATCH*3*5120);
    idwt_k<<<dim3(20,1,BATCH),256>>>(ll40, h2, ll80, 40, 128);
    minmax_k<<<1,1024>>>(ll80, BATCH*80*256, thr);
    mask_k<<<dim3(20,1,BATCH),256>>>(h2, thr, mask2, 40, 128);
    pool_coarse_k<<<dim3(20,1,BATCH),256>>>(mask2, upm2, 40, 128);
    pool_fine_k<<<dim3(80,1,BATCH),256>>>(mask2, cam2, wm2, 40, 128);

    { int t=256*384;   pack_w_k<<<dim3((t+255)/256,9),256>>>(u3w, p3h, p3l, 138, 372, 384, 3456, t); }
    { int t = BATCH*372*80*256;
      feat_pack_k<<<(t+255)/256,256>>>(xa, x4, upm2, cam2, feat0, 276, 96, 80, 256, t); }
    // up3 (reflect): 372->138, MT3 Mtiles=2 (192 rows), S=1, fused epilogue
    conv_hmma<1,3><<<dim3(160, 2, BATCH), 256, CONV_SMEM>>>(p3h, p3l, feat0, xb,
        372, 384, 138, 80, 256, 3456, 1, u3b, wm2, 1);
    conv_small_part<3,0><<<dim3(160,4,BATCH),128>>>(xb, w3w, h3, 138, 4, 80, 256);
    finalize_small<<<(BATCH*3*20480+255)/256,256>>>(h3, w3b, mask2, 3, 80, 256, 1.f, BATCH*3*20480);
    idwt_k<<<dim3(80,1,BATCH),256>>>(ll80, h3, (float*)d_out, 80, 256);
}

// round 16
// speedup vs baseline: 1.2691x; 1.0534x over previous
#include <cuda_runtime.h>
#include <cuda_bf16.h>
#include <math.h>
#include <stdint.h>

#define BATCH 4

__device__ __forceinline__ uint32_t smem_u32(const void* p){
    uint32_t a; asm("{ .reg .u64 t; cvta.to.shared.u64 t, %1; cvt.u32.u64 %0, t; }":"=r"(a):"l"(p)); return a;
}
__device__ __forceinline__ void ldsm4(uint32_t& r0, uint32_t& r1, uint32_t& r2, uint32_t& r3, uint32_t a){
    asm volatile("ldmatrix.sync.aligned.m8n8.x4.shared.b16 {%0,%1,%2,%3}, [%4];"
        :"=r"(r0),"=r"(r1),"=r"(r2),"=r"(r3):"r"(a));
}
__device__ __forceinline__ void mma16816(float* c, const uint32_t* a, const uint32_t* b){
    asm volatile("mma.sync.aligned.m16n8k16.row.col.f32.bf16.bf16.f32 "
        "{%0,%1,%2,%3}, {%4,%5,%6,%7}, {%8,%9}, {%0,%1,%2,%3};"
        : "+f"(c[0]),"+f"(c[1]),"+f"(c[2]),"+f"(c[3])
        : "r"(a[0]),"r"(a[1]),"r"(a[2]),"r"(a[3]),"r"(b[0]),"r"(b[1]));
}
__device__ __forceinline__ void cpasync16(uint32_t saddr, const void* g){
    asm volatile("cp.async.cg.shared.global [%0], [%1], 16;"::"r"(saddr),"l"(g));
}
__device__ __forceinline__ void cpcommit(){ asm volatile("cp.async.commit_group;"); }
__device__ __forceinline__ void cpwait0(){ asm volatile("cp.async.wait_group 0;"); }
__device__ __forceinline__ uint32_t packf(float v){
    __nv_bfloat16 h = __float2bfloat16(v);
    __nv_bfloat16 l = __float2bfloat16(v - __bfloat162float(h));
    return (uint32_t)*(unsigned short*)&h | ((uint32_t)*(unsigned short*)&l << 16);
}

// ---------------- scratch ----------------
__device__ float g_xd0[BATCH*1104*10*32];
__device__ float g_xd1[BATCH*552*20*64];
__device__ float g_ll1[BATCH*20*64];
__device__ float g_h1[BATCH*3*20*64];
__device__ float g_ll40[BATCH*40*128];
__device__ float g_mask1[BATCH*20*64];
__device__ float g_upm1[BATCH*20*64];
__device__ float g_cam1[BATCH*40*128];
__device__ float g_wm1[BATCH*40*128];
__device__ float g_xa[BATCH*276*40*128];
__device__ float g_h2[BATCH*3*40*128];
__device__ float g_ll80[BATCH*80*256];
__device__ float g_mask2[BATCH*40*128];
__device__ float g_upm2[BATCH*40*128];
__device__ float g_cam2[BATCH*80*256];
__device__ float g_wm2[BATCH*80*256];
__device__ float g_xb[BATCH*138*80*256];
__device__ float g_h3[BATCH*3*80*256];
__device__ float g_thr[1];
// packed u32 (bf16 hi | lo<<16) conv inputs
__device__ __align__(16) uint32_t g_px32[BATCH*2208*10*32];
__device__ __align__(16) uint32_t g_cat1[BATCH*1488*20*64];
__device__ __align__(16) uint32_t g_feat1[BATCH*744*40*128];
__device__ __align__(16) uint32_t g_feat0[BATCH*372*80*256];
// packed weights (hi/lo planes), K reordered as t*ICpad+ic
__device__ __align__(16) __nv_bfloat16 g_w2h[1152*19872];
__device__ __align__(16) __nv_bfloat16 g_w2l[1152*19872];
__device__ __align__(16) __nv_bfloat16 g_u1h[640*13536];
__device__ __align__(16) __nv_bfloat16 g_u1l[640*13536];
__device__ __align__(16) __nv_bfloat16 g_u2h[384*6912];
__device__ __align__(16) __nv_bfloat16 g_u2l[384*6912];
__device__ __align__(16) __nv_bfloat16 g_u3h[256*3456];
__device__ __align__(16) __nv_bfloat16 g_u3l[256*3456];

// ---------------- weight pack: w[oc, ic*9+t] -> planes[ocpad, t*ICpad+ic] ----------------
__global__ void pack_w_k(const float* __restrict__ w, __nv_bfloat16* __restrict__ hi,
                         __nv_bfloat16* __restrict__ lo, int OC, int IC, int ICpad, int Kpad, int totRC)
{
    int i = blockIdx.x*256 + threadIdx.x;
    if (i >= totRC) return;
    int t = blockIdx.y;
    int r = i / ICpad, ic = i - r*ICpad;
    float v = (r < OC && ic < IC) ? w[(size_t)r*IC*9 + ic*9 + t] : 0.f;
    __nv_bfloat16 h = __float2bfloat16(v);
    size_t o = (size_t)r*Kpad + t*ICpad + ic;
    hi[o] = h;
    lo[o] = __float2bfloat16(v - __bfloat162float(h));
}

// ---------------- input pack ----------------
__global__ void pack_x_k(const float* __restrict__ x, uint32_t* __restrict__ o, int total)
{
    int i = blockIdx.x*256 + threadIdx.x;
    if (i < total) o[i] = packf(x[i]);
}

// ---------------- zero accumulators ----------------
__global__ void zero6_k(float* a,int na, float* b,int nb, float* c,int nc,
                        float* d,int nd, float* e,int ne, float* f,int nf)
{
    int i = blockIdx.x*256 + threadIdx.x;
    if (i < na) a[i] = 0.f;
    if (i < nb) b[i] = 0.f;
    if (i < nc) c[i] = 0.f;
    if (i < nd) d[i] = 0.f;
    if (i < ne) e[i] = 0.f;
    if (i < nf) f[i] = 0.f;
}

// ---------------- feat build + pack ----------------
__global__ void feat_pack_k(const float* __restrict__ xc, const float* __restrict__ skip,
                            const float* __restrict__ upm, const float* __restrict__ cam,
                            uint32_t* __restrict__ out, int C1, int C2, int Hf, int Wf, int total)
{
    int idx = blockIdx.x*256 + threadIdx.x;
    if (idx >= total) return;
    int Wc = Wf >> 1, Hc = Hf >> 1;
    int x = idx % Wf; int t = idx / Wf;
    int y = t % Hf;  t /= Hf;
    int c = t % (C1+C2); int b = t / (C1+C2);
    float v;
    if (c < C1) {
        v = xc[((size_t)b*C1 + c)*Hc*Wc + (size_t)(y>>1)*Wc + (x>>1)];
        if (upm) v *= upm[(size_t)b*Hc*Wc + (size_t)(y>>1)*Wc + (x>>1)];
    } else {
        v = skip[((size_t)b*C2 + (c-C1))*Hf*Wf + (size_t)y*Wf + x];
    }
    if (cam) v *= cam[(size_t)b*Hf*Wf + (size_t)y*Wf + x];
    out[idx] = packf(v);
}

// ---------------- HMMA implicit-GEMM conv: K-chunk 32, double-buffered, 2 CTA/SM, staged gather ----------------
#define ROWB 80
#define S_AH 0
#define S_AL 10240
#define S_BH 20480
#define S_BL 30720
#define BUFSZ 40960
#define CONV_SMEM (2*BUFSZ)

template<int PAD, int MT, int TERMS>  // PAD: 1 reflect, 2 edge. M-tile = 32*MT rows. TERMS: 3 or 2.
__global__ __launch_bounds__(256, 2)
void conv_hmma(const __nv_bfloat16* __restrict__ Ah, const __nv_bfloat16* __restrict__ Al,
               const uint32_t* __restrict__ pin, float* __restrict__ out,
               int IC, int ICpad, int OC, int H, int W, int Kpad, int S,
               const float* __restrict__ bias, const float* __restrict__ mask, int leaky)
{
    extern __shared__ __align__(16) unsigned char sm[];
    const uint32_t sb = smem_u32(sm);
    const int tid = threadIdx.x, wid = tid >> 5, lane = tid & 31;
    const int HW = H * W;
    const int n0 = blockIdx.x * 128;
    const int Mtiles = gridDim.y / S;
    const int mt_id = blockIdx.y % Mtiles, ks = blockIdx.y / Mtiles;
    const int m0 = mt_id * (32*MT);
    const int b = blockIdx.z;

    const int chunks = Kpad >> 5;
    const int cseg = (chunks + S - 1) / S;
    const int c0 = ks * cseg, c1 = min(chunks, c0 + cseg);

    const uint32_t* inb = pin + (size_t)b * IC * HW;
    const int wm = (wid >> 2) * (16*MT), wn = (wid & 3) * 32;

    float acc[MT][4][4];
    #pragma unroll
    for (int i=0;i<MT;i++) for (int j=0;j<4;j++) for (int k=0;k<4;k++) acc[i][j][k]=0.f;

    const int mloc = tid >> 1, kh = tid & 1;
    const int nglob = n0 + mloc;
    const bool okpix = (nglob < HW);
    const int py = okpix ? nglob / W : 0;
    const int px_ = okpix ? nglob - py*W : 0;

    int kthr = (c0 << 5) + kh*16;
    int tap = kthr / ICpad;
    int icr = kthr - tap*ICpad;

    uint32_t bv[16];   // staged B values; LDG latency overlapped with compute

    auto issueA = [&](int c, int bo){
        const int kc = c << 5;
        #pragma unroll
        for (int i = 0; i < MT; ++i) {
            int flat = i*256 + tid;
            int fo = flat * 16;
            int plane = fo / (MT*2048);
            int rem = fo - plane*(MT*2048);
            int row = rem >> 6, col = rem & 63;
            const __nv_bfloat16* src = (plane ? Al : Ah) + (size_t)(m0+row)*Kpad + kc + (col>>1);
            cpasync16(sb + bo + (plane ? S_AL : S_AH) + row*ROWB + col, src);
        }
        cpcommit();
    };
    auto gatherRegs = [&](){
        int t3 = (tap*11) >> 5;
        int dy = t3 - 1, dx = tap - t3*3 - 1;
        int yy = py + dy, xx = px_ + dx;
        if (PAD == 1) {
            yy = yy<0 ? -yy : (yy>=H ? 2*H-2-yy : yy);
            xx = xx<0 ? -xx : (xx>=W ? 2*W-2-xx : xx);
        } else {
            yy = min(max(yy,0),H-1); xx = min(max(xx,0),W-1);
        }
        const uint32_t* p = inb + (size_t)icr*HW + yy*W + xx;
        #pragma unroll
        for (int e = 0; e < 16; ++e)
            bv[e] = (okpix && (icr + e) < IC) ? __ldg(p + (size_t)e*HW) : 0u;
        icr += 32;
        if (icr >= ICpad) { icr -= ICpad; ++tap; }
    };
    auto stsB = [&](int bo){
        int d = bo + mloc*ROWB + kh*32;
        #pragma unroll
        for (int g8 = 0; g8 < 2; ++g8) {
            uint32_t* v = bv + g8*8;
            uint32_t hp0 = __byte_perm(v[0],v[1],0x5410), hp1 = __byte_perm(v[2],v[3],0x5410);
            uint32_t hp2 = __byte_perm(v[4],v[5],0x5410), hp3 = __byte_perm(v[6],v[7],0x5410);
            *(uint4*)(sm + d + S_BH + g8*16) = make_uint4(hp0,hp1,hp2,hp3);
            if (TERMS == 3) {
                uint32_t lp0 = __byte_perm(v[0],v[1],0x7632), lp1 = __byte_perm(v[2],v[3],0x7632);
                uint32_t lp2 = __byte_perm(v[4],v[5],0x7632), lp3 = __byte_perm(v[6],v[7],0x7632);
                *(uint4*)(sm + d + S_BL + g8*16) = make_uint4(lp0,lp1,lp2,lp3);
            }
        }
    };

    issueA(c0, 0);
    gatherRegs();

    for (int c = c0; c < c1; ++c) {
        const int bo = ((c - c0) & 1) * BUFSZ;
        const int bn = BUFSZ - bo;
        stsB(bo);          // B STS issues while A cp.async completes (disjoint regions)
        cpwait0();
        __syncthreads();
        if (c + 1 < c1) {
            issueA(c + 1, bn);
            gatherRegs();
        }
        #pragma unroll
        for (int kk = 0; kk < 2; ++kk) {
            uint32_t bh[4][2], bl[4][2];
            #pragma unroll
            for (int nt2 = 0; nt2 < 2; ++nt2) {
                int g = lane >> 3;
                int brow = wn + nt2*16 + (lane & 7) + ((g & 2) ? 8 : 0);
                uint32_t baddr = sb + bo + brow*ROWB + kk*32 + ((g & 1) ? 16 : 0);
                ldsm4(bh[nt2*2][0], bh[nt2*2][1], bh[nt2*2+1][0], bh[nt2*2+1][1], baddr + S_BH);
                if (TERMS == 3)
                    ldsm4(bl[nt2*2][0], bl[nt2*2][1], bl[nt2*2+1][0], bl[nt2*2+1][1], baddr + S_BL);
            }
            #pragma unroll
            for (int mt = 0; mt < MT; ++mt) {
                int arow = wm + mt*16 + (lane & 15);
                uint32_t aaddr = sb + bo + arow*ROWB + kk*32 + ((lane >> 4) ? 16 : 0);
                uint32_t ah[4], al[4];
                ldsm4(ah[0], ah[1], ah[2], ah[3], aaddr + S_AH);
                ldsm4(al[0], al[1], al[2], al[3], aaddr + S_AL);
                #pragma unroll
                for (int nt = 0; nt < 4; ++nt) {
                    mma16816(acc[mt][nt], ah, bh[nt]);
                    if (TERMS == 3) mma16816(acc[mt][nt], ah, bl[nt]);
                    mma16816(acc[mt][nt], al, bh[nt]);
                }
            }
        }
    }

    // ---- epilogue ----
    float* ob = out + (size_t)b * OC * HW;
    const float* mb = mask ? mask + (size_t)b*HW : nullptr;
    const bool direct = (S == 1);
    #pragma unroll
    for (int mt = 0; mt < MT; ++mt) {
        #pragma unroll
        for (int nt = 0; nt < 4; ++nt) {
            #pragma unroll
            for (int cr = 0; cr < 4; ++cr) {
                int r = wm + mt*16 + (lane >> 2) + ((cr >= 2) ? 8 : 0);
                int col = wn + nt*8 + (lane & 3)*2 + (cr & 1);
                int oc = m0 + r, px = n0 + col;
                if (oc < OC && px < HW) {
                    float v = acc[mt][nt][cr];
                    if (direct) {
                        if (bias) v += bias[oc];
                        if (leaky) v = v > 0.f ? v : 0.2f*v;
                        if (mb) v *= mb[px];
                        ob[(size_t)oc*HW + px] = v;
                    } else {
                        atomicAdd(ob + (size_t)oc*HW + px, v);
                    }
                }
            }
        }
    }
}

// ---------------- finalize big ----------------
__global__ void finalize_big(float* __restrict__ buf, const float* __restrict__ bias,
                             const float* __restrict__ mask, int C, int HW, int leaky, int total)
{
    int i = blockIdx.x*256 + threadIdx.x;
    if (i >= total) return;
    int p = i % HW, t = i / HW, c = t % C, b = t / C;
    float v = buf[i] + bias[c];
    if (leaky) v = v > 0.f ? v : 0.2f*v;
    if (mask) v *= mask[(size_t)b*HW + p];
    buf[i] = v;
}

// ---------------- small conv partial ----------------
template<int NOUT, int PAD>
__global__ void conv_small_part(const float* __restrict__ in, const float* __restrict__ wgt,
                                float* __restrict__ acc, int IC, int nsp, int H, int W)
{
    int b = blockIdx.z, sp = blockIdx.y;
    int HW = H*W;
    int p = blockIdx.x*128 + threadIdx.x;
    if (p >= HW) return;
    int y = p / W, x = p - y*W;
    int icPer = (IC + nsp - 1)/nsp, ic0 = sp*icPer, ic1 = min(IC, ic0+icPer);
    float a[NOUT];
    #pragma unroll
    for (int j = 0; j < NOUT; ++j) a[j] = 0.f;
    const float* inb = in + (size_t)b*IC*HW;
    for (int ic = ic0; ic < ic1; ++ic) {
        const float* ip = inb + (size_t)ic*HW;
        const float* wp = wgt + (size_t)ic*9;
        #pragma unroll
        for (int t = 0; t < 9; ++t) {
            int yy = y + t/3 - 1, xx = x + t%3 - 1;
            float v;
            if (PAD == 0) v = (yy>=0 && yy<H && xx>=0 && xx<W) ? __ldg(ip + yy*W + xx) : 0.f;
            else { yy = min(max(yy,0),H-1); xx = min(max(xx,0),W-1); v = __ldg(ip + yy*W + xx); }
            #pragma unroll
            for (int j = 0; j < NOUT; ++j)
                a[j] = fmaf(v, __ldg(wp + (size_t)j*IC*9 + t), a[j]);
        }
    }
    #pragma unroll
    for (int j = 0; j < NOUT; ++j)
        atomicAdd(acc + ((size_t)b*NOUT + j)*HW + p, a[j]);
}

__global__ void finalize_small(float* __restrict__ buf, const float* __restrict__ bias,
                               const float* __restrict__ mask, int NOUT, int H, int W,
                               float scale, int total)
{
    int i = blockIdx.x*256 + threadIdx.x;
    if (i >= total) return;
    int HW = H*W;
    int p = i % HW, t = i / HW, c = t % NOUT, b = t / NOUT;
    float v = (buf[i] + bias[c]) * scale;
    if (mask) {
        int y = p / W, x = p - y*W;
        v *= mask[(size_t)b*(HW/4) + (y>>1)*(W>>1) + (x>>1)];
    }
    buf[i] = v;
}

// ---------------- glue ----------------
__global__ void idwt_k(const float* __restrict__ ll, const float* __restrict__ h,
                       float* __restrict__ out, int Hc, int Wc)
{
    int b = blockIdx.z;
    int p = blockIdx.x*256 + threadIdx.x;
    if (p >= Hc*Wc) return;
    int y = p / Wc, x = p - y*Wc;
    float l = ll[(size_t)b*Hc*Wc + p];
    const float* hb = h + (size_t)b*3*Hc*Wc;
    float lh = hb[p], hl = hb[Hc*Wc+p], hh = hb[2*Hc*Wc+p];
    float a = (l+lh)*0.5f, c2 = (l-lh)*0.5f, d2 = (hl+hh)*0.5f, e = (hl-hh)*0.5f;
    float* ob = out + (size_t)b*(2*Hc)*(2*Wc);
    int W2 = 2*Wc;
    ob[(size_t)(2*y)*W2 + 2*x]     = a + d2;
    ob[(size_t)(2*y)*W2 + 2*x+1]   = c2 + e;
    ob[(size_t)(2*y+1)*W2 + 2*x]   = a - d2;
    ob[(size_t)(2*y+1)*W2 + 2*x+1] = c2 - e;
}
__global__ void minmax_k(const float* __restrict__ d, int n, float* __restrict__ thr)
{
    __shared__ float smn[1024], smx[1024];
    int tid = threadIdx.x;
    float mn = 3.4e38f, mx = -3.4e38f;
    for (int i = tid; i < n; i += 1024) { float v = d[i]; mn = fminf(mn,v); mx = fmaxf(mx,v); }
    smn[tid]=mn; smx[tid]=mx; __syncthreads();
    for (int s=512; s>0; s>>=1) {
        if (tid<s){ smn[tid]=fminf(smn[tid],smn[tid+s]); smx[tid]=fmaxf(smx[tid],smx[tid+s]); }
        __syncthreads();
    }
    if (tid==0) thr[0] = (smx[0]-smn[0])*0.1f;
}
__global__ void mask_k(const float* __restrict__ h, const float* __restrict__ thr,
                       float* __restrict__ mask, int Hc, int Wc)
{
    int b = blockIdx.z;
    int p = blockIdx.x*256 + threadIdx.x;
    if (p >= Hc*Wc) return;
    const float* hb = h + (size_t)b*3*Hc*Wc;
    float m = fmaxf(fabsf(hb[p]), fmaxf(fabsf(hb[Hc*Wc+p]), fabsf(hb[2*Hc*Wc+p])));
    mask[(size_t)b*Hc*Wc + p] = (m > thr[0]) ? 1.f : 0.f;
}
__global__ void pool_coarse_k(const float* __restrict__ mask, float* __restrict__ upm, int Hc, int Wc)
{
    int b = blockIdx.z;
    int p = blockIdx.x*256 + threadIdx.x;
    if (p >= Hc*Wc) return;
    int y = p / Wc, x = p - y*Wc;
    const float* mb = mask + (size_t)b*Hc*Wc;
    float r = 0.f;
    for (int dy=-2;dy<=2;dy++){ int yy=y+dy; if (yy<0||yy>=Hc) continue;
      for (int dx=-2;dx<=2;dx++){ int xx=x+dx; if (xx<0||xx>=Wc) continue;
        r = fmaxf(r, mb[yy*Wc+xx]); } }
    upm[(size_t)b*Hc*Wc + p] = (r > 0.f) ? 1.f : 0.f;
}
__global__ void pool_fine_k(const float* __restrict__ mask, float* __restrict__ cam,
                            float* __restrict__ wm, int Hc, int Wc)
{
    int b = blockIdx.z;
    int Hf = 2*Hc, Wf = 2*Wc;
    int p = blockIdx.x*256 + threadIdx.x;
    if (p >= Hf*Wf) return;
    int y = p / Wf, x = p - y*Wf;
    const float* mb = mask + (size_t)b*Hc*Wc;
    float c5 = 0.f, c3 = 0.f;
    for (int dy=-2;dy<=2;dy++){ int fy=y+dy; if (fy<0||fy>=Hf) continue;
      for (int dx=-2;dx<=2;dx++){ int fx=x+dx; if (fx<0||fx>=Wf) continue;
        float v = mb[(fy>>1)*Wc + (fx>>1)];
        c5 = fmaxf(c5, v);
        if (dy>=-1 && dy<=1 && dx>=-1 && dx<=1) c3 = fmaxf(c3, v);
      } }
    cam[(size_t)b*Hf*Wf + p] = (c5 > 0.f) ? 1.f : 0.f;
    wm [(size_t)b*Hf*Wf + p] = (c3 > 0.f) ? 1.f : 0.f;
}

// =======================================================================
extern "C" void kernel_launch(void* const* d_in, const int* in_sizes, int n_in,
                              void* d_out, int out_size)
{
    const float* x32 = (const float*)d_in[0];
    const float* x16 = (const float*)d_in[1];
    const float* x8  = (const float*)d_in[2];
    const float* x4  = (const float*)d_in[3];
    const float* c2w = (const float*)d_in[4];  const float* c2b = (const float*)d_in[5];
    const float* u1w = (const float*)d_in[6];  const float* u1b = (const float*)d_in[7];
    const float* wllw= (const float*)d_in[8];  const float* wllb= (const float*)d_in[9];
    const float* w1w = (const float*)d_in[10]; const float* w1b = (const float*)d_in[11];
    const float* u2w = (const float*)d_in[12]; const float* u2b = (const float*)d_in[13];
    const float* w2w = (const float*)d_in[14]; const float* w2b = (const float*)d_in[15];
    const float* u3w = (const float*)d_in[16]; const float* u3b = (const float*)d_in[17];
    const float* w3w = (const float*)d_in[18]; const float* w3b = (const float*)d_in[19];

    float *xd0,*xd1,*ll1,*h1,*ll40,*mask1,*upm1,*cam1,*wm1;
    float *xa,*h2,*ll80,*mask2,*upm2,*cam2,*wm2,*xb,*h3,*thr;
    uint32_t *px32,*cat1,*feat1,*feat0;
    __nv_bfloat16 *w2h,*w2l,*p1h,*p1l,*p2h,*p2l,*p3h,*p3l;
    cudaGetSymbolAddress((void**)&xd0,g_xd0);   cudaGetSymbolAddress((void**)&xd1,g_xd1);
    cudaGetSymbolAddress((void**)&ll1,g_ll1);   cudaGetSymbolAddress((void**)&h1,g_h1);
    cudaGetSymbolAddress((void**)&ll40,g_ll40); cudaGetSymbolAddress((void**)&mask1,g_mask1);
    cudaGetSymbolAddress((void**)&upm1,g_upm1); cudaGetSymbolAddress((void**)&cam1,g_cam1);
    cudaGetSymbolAddress((void**)&wm1,g_wm1);   cudaGetSymbolAddress((void**)&xa,g_xa);
    cudaGetSymbolAddress((void**)&h2,g_h2);     cudaGetSymbolAddress((void**)&ll80,g_ll80);
    cudaGetSymbolAddress((void**)&mask2,g_mask2); cudaGetSymbolAddress((void**)&upm2,g_upm2);
    cudaGetSymbolAddress((void**)&cam2,g_cam2); cudaGetSymbolAddress((void**)&wm2,g_wm2);
    cudaGetSymbolAddress((void**)&xb,g_xb);     cudaGetSymbolAddress((void**)&h3,g_h3);
    cudaGetSymbolAddress((void**)&thr,g_thr);
    cudaGetSymbolAddress((void**)&px32,g_px32); cudaGetSymbolAddress((void**)&cat1,g_cat1);
    cudaGetSymbolAddress((void**)&feat1,g_feat1); cudaGetSymbolAddress((void**)&feat0,g_feat0);
    cudaGetSymbolAddress((void**)&w2h,g_w2h);   cudaGetSymbolAddress((void**)&w2l,g_w2l);
    cudaGetSymbolAddress((void**)&p1h,g_u1h);   cudaGetSymbolAddress((void**)&p1l,g_u1l);
    cudaGetSymbolAddress((void**)&p2h,g_u2h);   cudaGetSymbolAddress((void**)&p2l,g_u2l);
    cudaGetSymbolAddress((void**)&p3h,g_u3h);   cudaGetSymbolAddress((void**)&p3l,g_u3l);

    cudaFuncSetAttribute(conv_hmma<2,4,3>, cudaFuncAttributeMaxDynamicSharedMemorySize, CONV_SMEM);
    cudaFuncSetAttribute(conv_hmma<1,3,3>, cudaFuncAttributeMaxDynamicSharedMemorySize, CONV_SMEM);
    cudaFuncSetAttribute(conv_hmma<1,3,2>, cudaFuncAttributeMaxDynamicSharedMemorySize, CONV_SMEM);

    // launches 1-3 (profiled slot 4 = conv2)
    { int t=1152*2208; pack_w_k<<<dim3((t+255)/256,9),256>>>(c2w, w2h, w2l, 1104, 2208, 2208, 19872, t); }
    { int t=BATCH*2208*320; pack_x_k<<<(t+255)/256,256>>>(x32, px32, t); }
    zero6_k<<<(BATCH*552*1280+255)/256,256>>>(xd0, BATCH*1104*320, xd1, BATCH*552*1280,
                                              ll1, BATCH*1280, h1, BATCH*3*1280,
                                              h2, BATCH*3*5120, h3, BATCH*3*20480);

    // 4: conv2 (edge): 2208->1104, 10x32, MT4 Mtiles=9, S=8, 3-term
    conv_hmma<2,4,3><<<dim3(3, 9*8, BATCH), 256, CONV_SMEM>>>(w2h, w2l, px32, xd0,
        2208, 2208, 1104, 10, 32, 19872, 8, nullptr, nullptr, 0);
    finalize_big<<<(BATCH*1104*320+255)/256,256>>>(xd0, c2b, nullptr, 1104, 320, 0, BATCH*1104*320);

    { int t=640*1504;  pack_w_k<<<dim3((t+255)/256,9),256>>>(u1w, p1h, p1l, 552, 1488, 1504, 13536, t); }
    { int t = BATCH*1488*20*64;
      feat_pack_k<<<(t+255)/256,256>>>(xd0, x16, nullptr, nullptr, cat1, 1104, 384, 20, 64, t); }
    // up1 (reflect): 1488->552, MT3 Mtiles=6 (576 rows), S=4, 3-term
    conv_hmma<1,3,3><<<dim3(10, 6*4, BATCH), 256, CONV_SMEM>>>(p1h, p1l, cat1, xd1,
        1488, 1504, 552, 20, 64, 13536, 4, nullptr, nullptr, 0);
    finalize_big<<<(BATCH*552*1280+255)/256,256>>>(xd1, u1b, nullptr, 552, 1280, 1, BATCH*552*1280);
    conv_small_part<1,2><<<dim3(10,12,BATCH),128>>>(xd1, wllw, ll1, 552, 12, 20, 64);
    conv_small_part<3,0><<<dim3(10,12,BATCH),128>>>(xd1, w1w, h1, 552, 12, 20, 64);
    finalize_small<<<(BATCH*1280+255)/256,256>>>(ll1, wllb, nullptr, 1, 20, 64, 8.f, BATCH*1280);
    finalize_small<<<(BATCH*3*1280+255)/256,256>>>(h1, w1b, nullptr, 3, 20, 64, 4.f, BATCH*3*1280);
    idwt_k<<<dim3(5,1,BATCH),256>>>(ll1, h1, ll40, 20, 64);
    minmax_k<<<1,1024>>>(ll40, BATCH*40*128, thr);
    mask_k<<<dim3(5,1,BATCH),256>>>(h1, thr, mask1, 20, 64);
    pool_coarse_k<<<dim3(5,1,BATCH),256>>>(mask1, upm1, 20, 64);
    pool_fine_k<<<dim3(20,1,BATCH),256>>>(mask1, cam1, wm1, 20, 64);

    { int t=384*768;   pack_w_k<<<dim3((t+255)/256,9),256>>>(u2w, p2h, p2l, 276, 744, 768, 6912, t); }
    { int t = BATCH*744*40*128;
      feat_pack_k<<<(t+255)/256,256>>>(xd1, x8, upm1, cam1, feat1, 552, 192, 40, 128, t); }
    // up2 (reflect): 744->276, MT3 Mtiles=3 (288 rows), S=1, fused epilogue, 3-term
    conv_hmma<1,3,3><<<dim3(40, 3, BATCH), 256, CONV_SMEM>>>(p2h, p2l, feat1, xa,
        744, 768, 276, 40, 128, 6912, 1, u2b, wm1, 1);
    conv_small_part<3,0><<<dim3(40,8,BATCH),128>>>(xa, w2w, h2, 276, 8, 40, 128);
    finalize_small<<<(BATCH*3*5120+255)/256,256>>>(h2, w2b, mask1, 3, 40, 128, 2.f, BATCH*3*5120);
    idwt_k<<<dim3(20,1,BATCH),256>>>(ll40, h2, ll80, 40, 128);
    minmax_k<<<1,1024>>>(ll80, BATCH*80*256, thr);
    mask_k<<<dim3(20,1,BATCH),256>>>(h2, thr, mask2, 40, 128);
    pool_coarse_k<<<dim3(20,1,BATCH),256>>>(mask2, upm2, 40, 128);
    pool_fine_k<<<dim3(80,1,BATCH),256>>>(mask2, cam2, wm2, 40, 128);

    { int t=256*384;   pack_w_k<<<dim3((t+255)/256,9),256>>>(u3w, p3h, p3l, 138, 372, 384, 3456, t); }
    { int t = BATCH*372*80*256;
      feat_pack_k<<<(t+255)/256,256>>>(xa, x4, upm2, cam2, feat0, 276, 96, 80, 256, t); }
    // up3 (reflect): 372->138, MT3 Mtiles=2 (192 rows), S=1, fused epilogue, 2-TERM
    conv_hmma<1,3,2><<<dim3(160, 2, BATCH), 256, CONV_SMEM>>>(p3h, p3l, feat0, xb,
        372, 384, 138, 80, 256, 3456, 1, u3b, wm2, 1);
    conv_small_part<3,0><<<dim3(160,4,BATCH),128>>>(xb, w3w, h3, 138, 4, 80, 256);
    finalize_small<<<(BATCH*3*20480+255)/256,256>>>(h3, w3b, mask2, 3, 80, 256, 1.f, BATCH*3*20480);
    idwt_k<<<dim3(80,1,BATCH),256>>>(ll80, h3, (float*)d_out, 80, 256);
}

// round 17
// speedup vs baseline: 1.3170x; 1.0377x over previous
#include <cuda_runtime.h>
#include <cuda_bf16.h>
#include <math.h>
#include <stdint.h>

#define BATCH 4

__device__ __forceinline__ uint32_t smem_u32(const void* p){
    uint32_t a; asm("{ .reg .u64 t; cvta.to.shared.u64 t, %1; cvt.u32.u64 %0, t; }":"=r"(a):"l"(p)); return a;
}
__device__ __forceinline__ void ldsm4(uint32_t& r0, uint32_t& r1, uint32_t& r2, uint32_t& r3, uint32_t a){
    asm volatile("ldmatrix.sync.aligned.m8n8.x4.shared.b16 {%0,%1,%2,%3}, [%4];"
        :"=r"(r0),"=r"(r1),"=r"(r2),"=r"(r3):"r"(a));
}
__device__ __forceinline__ void mma16816(float* c, const uint32_t* a, const uint32_t* b){
    asm volatile("mma.sync.aligned.m16n8k16.row.col.f32.bf16.bf16.f32 "
        "{%0,%1,%2,%3}, {%4,%5,%6,%7}, {%8,%9}, {%0,%1,%2,%3};"
        : "+f"(c[0]),"+f"(c[1]),"+f"(c[2]),"+f"(c[3])
        : "r"(a[0]),"r"(a[1]),"r"(a[2]),"r"(a[3]),"r"(b[0]),"r"(b[1]));
}
__device__ __forceinline__ void cpasync16(uint32_t saddr, const void* g){
    asm volatile("cp.async.cg.shared.global [%0], [%1], 16;"::"r"(saddr),"l"(g));
}
__device__ __forceinline__ void cpcommit(){ asm volatile("cp.async.commit_group;"); }
__device__ __forceinline__ void cpwait0(){ asm volatile("cp.async.wait_group 0;"); }
__device__ __forceinline__ uint32_t packf(float v){
    __nv_bfloat16 h = __float2bfloat16(v);
    __nv_bfloat16 l = __float2bfloat16(v - __bfloat162float(h));
    return (uint32_t)*(unsigned short*)&h | ((uint32_t)*(unsigned short*)&l << 16);
}

// ---------------- scratch ----------------
__device__ float g_xd0[BATCH*1104*10*32];
__device__ float g_xd1[BATCH*552*20*64];
__device__ float g_ll1[BATCH*20*64];
__device__ float g_h1[BATCH*3*20*64];
__device__ float g_ll40[BATCH*40*128];
__device__ float g_mask1[BATCH*20*64];
__device__ float g_upm1[BATCH*20*64];
__device__ float g_cam1[BATCH*40*128];
__device__ float g_wm1[BATCH*40*128];
__device__ float g_xa[BATCH*276*40*128];
__device__ float g_h2[BATCH*3*40*128];
__device__ float g_ll80[BATCH*80*256];
__device__ float g_mask2[BATCH*40*128];
__device__ float g_upm2[BATCH*40*128];
__device__ float g_cam2[BATCH*80*256];
__device__ float g_wm2[BATCH*80*256];
__device__ float g_xb[BATCH*138*80*256];
__device__ float g_h3[BATCH*3*80*256];
__device__ float g_thr[1];
// packed u32 (bf16 hi | lo<<16) conv inputs
__device__ __align__(16) uint32_t g_px32[BATCH*2208*10*32];
__device__ __align__(16) uint32_t g_cat1[BATCH*1488*20*64];
__device__ __align__(16) uint32_t g_feat1[BATCH*744*40*128];
__device__ __align__(16) uint32_t g_feat0[BATCH*372*80*256];
// packed weights (hi/lo planes), K reordered as t*ICpad+ic
__device__ __align__(16) __nv_bfloat16 g_w2h[1152*19872];
__device__ __align__(16) __nv_bfloat16 g_w2l[1152*19872];
__device__ __align__(16) __nv_bfloat16 g_u1h[640*13536];
__device__ __align__(16) __nv_bfloat16 g_u1l[640*13536];
__device__ __align__(16) __nv_bfloat16 g_u2h[384*6912];
__device__ __align__(16) __nv_bfloat16 g_u2l[384*6912];
__device__ __align__(16) __nv_bfloat16 g_u3h[256*3456];
__device__ __align__(16) __nv_bfloat16 g_u3l[256*3456];

// ---------------- weight pack: w[oc, ic*9+t] -> planes[ocpad, t*ICpad+ic] ----------------
__global__ void pack_w_k(const float* __restrict__ w, __nv_bfloat16* __restrict__ hi,
                         __nv_bfloat16* __restrict__ lo, int OC, int IC, int ICpad, int Kpad, int totRC)
{
    int i = blockIdx.x*256 + threadIdx.x;
    if (i >= totRC) return;
    int t = blockIdx.y;
    int r = i / ICpad, ic = i - r*ICpad;
    float v = (r < OC && ic < IC) ? w[(size_t)r*IC*9 + ic*9 + t] : 0.f;
    __nv_bfloat16 h = __float2bfloat16(v);
    size_t o = (size_t)r*Kpad + t*ICpad + ic;
    hi[o] = h;
    lo[o] = __float2bfloat16(v - __bfloat162float(h));
}

// ---------------- input pack ----------------
__global__ void pack_x_k(const float* __restrict__ x, uint32_t* __restrict__ o, int total)
{
    int i = blockIdx.x*256 + threadIdx.x;
    if (i < total) o[i] = packf(x[i]);
}

// ---------------- zero accumulators ----------------
__global__ void zero6_k(float* a,int na, float* b,int nb, float* c,int nc,
                        float* d,int nd, float* e,int ne, float* f,int nf)
{
    int i = blockIdx.x*256 + threadIdx.x;
    if (i < na) a[i] = 0.f;
    if (i < nb) b[i] = 0.f;
    if (i < nc) c[i] = 0.f;
    if (i < nd) d[i] = 0.f;
    if (i < ne) e[i] = 0.f;
    if (i < nf) f[i] = 0.f;
}

// ---------------- feat build + pack ----------------
__global__ void feat_pack_k(const float* __restrict__ xc, const float* __restrict__ skip,
                            const float* __restrict__ upm, const float* __restrict__ cam,
                            uint32_t* __restrict__ out, int C1, int C2, int Hf, int Wf, int total)
{
    int idx = blockIdx.x*256 + threadIdx.x;
    if (idx >= total) return;
    int Wc = Wf >> 1, Hc = Hf >> 1;
    int x = idx % Wf; int t = idx / Wf;
    int y = t % Hf;  t /= Hf;
    int c = t % (C1+C2); int b = t / (C1+C2);
    float v;
    if (c < C1) {
        v = xc[((size_t)b*C1 + c)*Hc*Wc + (size_t)(y>>1)*Wc + (x>>1)];
        if (upm) v *= upm[(size_t)b*Hc*Wc + (size_t)(y>>1)*Wc + (x>>1)];
    } else {
        v = skip[((size_t)b*C2 + (c-C1))*Hf*Wf + (size_t)y*Wf + x];
    }
    if (cam) v *= cam[(size_t)b*Hf*Wf + (size_t)y*Wf + x];
    out[idx] = packf(v);
}

// ---------------- HMMA implicit-GEMM conv: K-chunk 32, double-buffered, 2 CTA/SM, staged gather ----------------
#define ROWB 80
#define S_AH 0
#define S_AL 10240
#define S_BH 20480
#define S_BL 30720
#define BUFSZ 40960
#define CONV_SMEM (2*BUFSZ)

// PAD: 1 reflect, 2 edge. MT: M-tile = 32*MT rows. TERMS: 3 or 2. FOLD: batch folded into N.
template<int PAD, int MT, int TERMS, int FOLD>
__global__ __launch_bounds__(256, 2)
void conv_hmma(const __nv_bfloat16* __restrict__ Ah, const __nv_bfloat16* __restrict__ Al,
               const uint32_t* __restrict__ pin, float* __restrict__ out,
               int IC, int ICpad, int OC, int H, int W, int BHW, int Kpad, int S,
               const float* __restrict__ bias, const float* __restrict__ mask, int leaky)
{
    extern __shared__ __align__(16) unsigned char sm[];
    const uint32_t sb = smem_u32(sm);
    const int tid = threadIdx.x, wid = tid >> 5, lane = tid & 31;
    const int HW = H * W;
    const int n0 = blockIdx.x * 128;
    const int Mtiles = gridDim.y / S;
    const int mt_id = blockIdx.y % Mtiles, ks = blockIdx.y / Mtiles;
    const int m0 = mt_id * (32*MT);
    const int bz = FOLD ? 0 : blockIdx.z;

    const int chunks = Kpad >> 5;
    const int cseg = (chunks + S - 1) / S;
    const int c0 = ks * cseg, c1 = min(chunks, c0 + cseg);

    const int wm = (wid >> 2) * (16*MT), wn = (wid & 3) * 32;

    float acc[MT][4][4];
    #pragma unroll
    for (int i=0;i<MT;i++) for (int j=0;j<4;j++) for (int k=0;k<4;k++) acc[i][j][k]=0.f;

    const int mloc = tid >> 1, kh = tid & 1;
    const int nglob = n0 + mloc;
    const bool okpix = (nglob < BHW);
    const int bix = FOLD ? (okpix ? nglob / HW : 0) : bz;
    const int pix = FOLD ? (okpix ? nglob - bix*HW : 0) : nglob;
    const int py = pix / W, px_ = pix - (pix/W)*W;
    const uint32_t* inb = pin + (size_t)bix * IC * HW;

    int kthr = (c0 << 5) + kh*16;
    int tap = kthr / ICpad;
    int icr = kthr - tap*ICpad;

    uint32_t bv[16];   // staged B values; LDG latency overlapped with compute

    auto issueA = [&](int c, int bo){
        const int kc = c << 5;
        #pragma unroll
        for (int i = 0; i < MT; ++i) {
            int flat = i*256 + tid;
            int fo = flat * 16;
            int plane = fo / (MT*2048);
            int rem = fo - plane*(MT*2048);
            int row = rem >> 6, col = rem & 63;
            const __nv_bfloat16* src = (plane ? Al : Ah) + (size_t)(m0+row)*Kpad + kc + (col>>1);
            cpasync16(sb + bo + (plane ? S_AL : S_AH) + row*ROWB + col, src);
        }
        cpcommit();
    };
    auto gatherRegs = [&](){
        int t3 = (tap*11) >> 5;
        int dy = t3 - 1, dx = tap - t3*3 - 1;
        int yy = py + dy, xx = px_ + dx;
        if (PAD == 1) {
            yy = yy<0 ? -yy : (yy>=H ? 2*H-2-yy : yy);
            xx = xx<0 ? -xx : (xx>=W ? 2*W-2-xx : xx);
        } else {
            yy = min(max(yy,0),H-1); xx = min(max(xx,0),W-1);
        }
        const uint32_t* p = inb + (size_t)icr*HW + yy*W + xx;
        #pragma unroll
        for (int e = 0; e < 16; ++e)
            bv[e] = (okpix && (icr + e) < IC) ? __ldg(p + (size_t)e*HW) : 0u;
        icr += 32;
        if (icr >= ICpad) { icr -= ICpad; ++tap; }
    };
    auto stsB = [&](int bo){
        int d = bo + mloc*ROWB + kh*32;
        #pragma unroll
        for (int g8 = 0; g8 < 2; ++g8) {
            uint32_t* v = bv + g8*8;
            uint32_t hp0 = __byte_perm(v[0],v[1],0x5410), hp1 = __byte_perm(v[2],v[3],0x5410);
            uint32_t hp2 = __byte_perm(v[4],v[5],0x5410), hp3 = __byte_perm(v[6],v[7],0x5410);
            *(uint4*)(sm + d + S_BH + g8*16) = make_uint4(hp0,hp1,hp2,hp3);
            if (TERMS == 3) {
                uint32_t lp0 = __byte_perm(v[0],v[1],0x7632), lp1 = __byte_perm(v[2],v[3],0x7632);
                uint32_t lp2 = __byte_perm(v[4],v[5],0x7632), lp3 = __byte_perm(v[6],v[7],0x7632);
                *(uint4*)(sm + d + S_BL + g8*16) = make_uint4(lp0,lp1,lp2,lp3);
            }
        }
    };

    issueA(c0, 0);
    gatherRegs();

    for (int c = c0; c < c1; ++c) {
        const int bo = ((c - c0) & 1) * BUFSZ;
        const int bn = BUFSZ - bo;
        stsB(bo);          // B STS issues while A cp.async completes (disjoint regions)
        cpwait0();
        __syncthreads();
        if (c + 1 < c1) {
            issueA(c + 1, bn);
            gatherRegs();
        }
        #pragma unroll
        for (int kk = 0; kk < 2; ++kk) {
            uint32_t bh[4][2], bl[4][2];
            #pragma unroll
            for (int nt2 = 0; nt2 < 2; ++nt2) {
                int g = lane >> 3;
                int brow = wn + nt2*16 + (lane & 7) + ((g & 2) ? 8 : 0);
                uint32_t baddr = sb + bo + brow*ROWB + kk*32 + ((g & 1) ? 16 : 0);
                ldsm4(bh[nt2*2][0], bh[nt2*2][1], bh[nt2*2+1][0], bh[nt2*2+1][1], baddr + S_BH);
                if (TERMS == 3)
                    ldsm4(bl[nt2*2][0], bl[nt2*2][1], bl[nt2*2+1][0], bl[nt2*2+1][1], baddr + S_BL);
            }
            #pragma unroll
            for (int mt = 0; mt < MT; ++mt) {
                int arow = wm + mt*16 + (lane & 15);
                uint32_t aaddr = sb + bo + arow*ROWB + kk*32 + ((lane >> 4) ? 16 : 0);
                uint32_t ah[4], al[4];
                ldsm4(ah[0], ah[1], ah[2], ah[3], aaddr + S_AH);
                ldsm4(al[0], al[1], al[2], al[3], aaddr + S_AL);
                #pragma unroll
                for (int nt = 0; nt < 4; ++nt) {
                    mma16816(acc[mt][nt], ah, bh[nt]);
                    if (TERMS == 3) mma16816(acc[mt][nt], ah, bl[nt]);
                    mma16816(acc[mt][nt], al, bh[nt]);
                }
            }
        }
    }

    // ---- epilogue ----
    const bool direct = (S == 1);
    #pragma unroll
    for (int mt = 0; mt < MT; ++mt) {
        #pragma unroll
        for (int nt = 0; nt < 4; ++nt) {
            #pragma unroll
            for (int cr = 0; cr < 4; ++cr) {
                int r = wm + mt*16 + (lane >> 2) + ((cr >= 2) ? 8 : 0);
                int col = wn + nt*8 + (lane & 3)*2 + (cr & 1);
                int oc = m0 + r, pxg = n0 + col;
                if (oc < OC && pxg < BHW) {
                    int bb = FOLD ? pxg / HW : bz;
                    int pp = FOLD ? pxg - bb*HW : pxg;
                    float v = acc[mt][nt][cr];
                    float* op = out + ((size_t)bb*OC + oc)*HW + pp;
                    if (direct) {
                        if (bias) v += bias[oc];
                        if (leaky) v = v > 0.f ? v : 0.2f*v;
                        if (mask) v *= mask[(size_t)bb*HW + pp];
                        *op = v;
                    } else {
                        atomicAdd(op, v);
                    }
                }
            }
        }
    }
}

// ---------------- finalize big ----------------
__global__ void finalize_big(float* __restrict__ buf, const float* __restrict__ bias,
                             const float* __restrict__ mask, int C, int HW, int leaky, int total)
{
    int i = blockIdx.x*256 + threadIdx.x;
    if (i >= total) return;
    int p = i % HW, t = i / HW, c = t % C, b = t / C;
    float v = buf[i] + bias[c];
    if (leaky) v = v > 0.f ? v : 0.2f*v;
    if (mask) v *= mask[(size_t)b*HW + p];
    buf[i] = v;
}

// ---------------- small conv partial ----------------
template<int NOUT, int PAD>
__global__ void conv_small_part(const float* __restrict__ in, const float* __restrict__ wgt,
                                float* __restrict__ acc, int IC, int nsp, int H, int W)
{
    int b = blockIdx.z, sp = blockIdx.y;
    int HW = H*W;
    int p = blockIdx.x*128 + threadIdx.x;
    if (p >= HW) return;
    int y = p / W, x = p - y*W;
    int icPer = (IC + nsp - 1)/nsp, ic0 = sp*icPer, ic1 = min(IC, ic0+icPer);
    float a[NOUT];
    #pragma unroll
    for (int j = 0; j < NOUT; ++j) a[j] = 0.f;
    const float* inb = in + (size_t)b*IC*HW;
    for (int ic = ic0; ic < ic1; ++ic) {
        const float* ip = inb + (size_t)ic*HW;
        const float* wp = wgt + (size_t)ic*9;
        #pragma unroll
        for (int t = 0; t < 9; ++t) {
            int yy = y + t/3 - 1, xx = x + t%3 - 1;
            float v;
            if (PAD == 0) v = (yy>=0 && yy<H && xx>=0 && xx<W) ? __ldg(ip + yy*W + xx) : 0.f;
            else { yy = min(max(yy,0),H-1); xx = min(max(xx,0),W-1); v = __ldg(ip + yy*W + xx); }
            #pragma unroll
            for (int j = 0; j < NOUT; ++j)
                a[j] = fmaf(v, __ldg(wp + (size_t)j*IC*9 + t), a[j]);
        }
    }
    #pragma unroll
    for (int j = 0; j < NOUT; ++j)
        atomicAdd(acc + ((size_t)b*NOUT + j)*HW + p, a[j]);
}

__global__ void finalize_small(float* __restrict__ buf, const float* __restrict__ bias,
                               const float* __restrict__ mask, int NOUT, int H, int W,
                               float scale, int total)
{
    int i = blockIdx.x*256 + threadIdx.x;
    if (i >= total) return;
    int HW = H*W;
    int p = i % HW, t = i / HW, c = t % NOUT, b = t / NOUT;
    float v = (buf[i] + bias[c]) * scale;
    if (mask) {
        int y = p / W, x = p - y*W;
        v *= mask[(size_t)b*(HW/4) + (y>>1)*(W>>1) + (x>>1)];
    }
    buf[i] = v;
}

// ---------------- glue ----------------
__global__ void idwt_k(const float* __restrict__ ll, const float* __restrict__ h,
                       float* __restrict__ out, int Hc, int Wc)
{
    int b = blockIdx.z;
    int p = blockIdx.x*256 + threadIdx.x;
    if (p >= Hc*Wc) return;
    int y = p / Wc, x = p - y*Wc;
    float l = ll[(size_t)b*Hc*Wc + p];
    const float* hb = h + (size_t)b*3*Hc*Wc;
    float lh = hb[p], hl = hb[Hc*Wc+p], hh = hb[2*Hc*Wc+p];
    float a = (l+lh)*0.5f, c2 = (l-lh)*0.5f, d2 = (hl+hh)*0.5f, e = (hl-hh)*0.5f;
    float* ob = out + (size_t)b*(2*Hc)*(2*Wc);
    int W2 = 2*Wc;
    ob[(size_t)(2*y)*W2 + 2*x]     = a + d2;
    ob[(size_t)(2*y)*W2 + 2*x+1]   = c2 + e;
    ob[(size_t)(2*y+1)*W2 + 2*x]   = a - d2;
    ob[(size_t)(2*y+1)*W2 + 2*x+1] = c2 - e;
}
__global__ void minmax_k(const float* __restrict__ d, int n, float* __restrict__ thr)
{
    __shared__ float smn[1024], smx[1024];
    int tid = threadIdx.x;
    float mn = 3.4e38f, mx = -3.4e38f;
    for (int i = tid; i < n; i += 1024) { float v = d[i]; mn = fminf(mn,v); mx = fmaxf(mx,v); }
    smn[tid]=mn; smx[tid]=mx; __syncthreads();
    for (int s=512; s>0; s>>=1) {
        if (tid<s){ smn[tid]=fminf(smn[tid],smn[tid+s]); smx[tid]=fmaxf(smx[tid],smx[tid+s]); }
        __syncthreads();
    }
    if (tid==0) thr[0] = (smx[0]-smn[0])*0.1f;
}
__global__ void mask_k(const float* __restrict__ h, const float* __restrict__ thr,
                       float* __restrict__ mask, int Hc, int Wc)
{
    int b = blockIdx.z;
    int p = blockIdx.x*256 + threadIdx.x;
    if (p >= Hc*Wc) return;
    const float* hb = h + (size_t)b*3*Hc*Wc;
    float m = fmaxf(fabsf(hb[p]), fmaxf(fabsf(hb[Hc*Wc+p]), fabsf(hb[2*Hc*Wc+p])));
    mask[(size_t)b*Hc*Wc + p] = (m > thr[0]) ? 1.f : 0.f;
}
__global__ void pool_coarse_k(const float* __restrict__ mask, float* __restrict__ upm, int Hc, int Wc)
{
    int b = blockIdx.z;
    int p = blockIdx.x*256 + threadIdx.x;
    if (p >= Hc*Wc) return;
    int y = p / Wc, x = p - y*Wc;
    const float* mb = mask + (size_t)b*Hc*Wc;
    float r = 0.f;
    for (int dy=-2;dy<=2;dy++){ int yy=y+dy; if (yy<0||yy>=Hc) continue;
      for (int dx=-2;dx<=2;dx++){ int xx=x+dx; if (xx<0||xx>=Wc) continue;
        r = fmaxf(r, mb[yy*Wc+xx]); } }
    upm[(size_t)b*Hc*Wc + p] = (r > 0.f) ? 1.f : 0.f;
}
__global__ void pool_fine_k(const float* __restrict__ mask, float* __restrict__ cam,
                            float* __restrict__ wm, int Hc, int Wc)
{
    int b = blockIdx.z;
    int Hf = 2*Hc, Wf = 2*Wc;
    int p = blockIdx.x*256 + threadIdx.x;
    if (p >= Hf*Wf) return;
    int y = p / Wf, x = p - y*Wf;
    const float* mb = mask + (size_t)b*Hc*Wc;
    float c5 = 0.f, c3 = 0.f;
    for (int dy=-2;dy<=2;dy++){ int fy=y+dy; if (fy<0||fy>=Hf) continue;
      for (int dx=-2;dx<=2;dx++){ int fx=x+dx; if (fx<0||fx>=Wf) continue;
        float v = mb[(fy>>1)*Wc + (fx>>1)];
        c5 = fmaxf(c5, v);
        if (dy>=-1 && dy<=1 && dx>=-1 && dx<=1) c3 = fmaxf(c3, v);
      } }
    cam[(size_t)b*Hf*Wf + p] = (c5 > 0.f) ? 1.f : 0.f;
    wm [(size_t)b*Hf*Wf + p] = (c3 > 0.f) ? 1.f : 0.f;
}

// =======================================================================
extern "C" void kernel_launch(void* const* d_in, const int* in_sizes, int n_in,
                              void* d_out, int out_size)
{
    const float* x32 = (const float*)d_in[0];
    const float* x16 = (const float*)d_in[1];
    const float* x8  = (const float*)d_in[2];
    const float* x4  = (const float*)d_in[3];
    const float* c2w = (const float*)d_in[4];  const float* c2b = (const float*)d_in[5];
    const float* u1w = (const float*)d_in[6];  const float* u1b = (const float*)d_in[7];
    const float* wllw= (const float*)d_in[8];  const float* wllb= (const float*)d_in[9];
    const float* w1w = (const float*)d_in[10]; const float* w1b = (const float*)d_in[11];
    const float* u2w = (const float*)d_in[12]; const float* u2b = (const float*)d_in[13];
    const float* w2w = (const float*)d_in[14]; const float* w2b = (const float*)d_in[15];
    const float* u3w = (const float*)d_in[16]; const float* u3b = (const float*)d_in[17];
    const float* w3w = (const float*)d_in[18]; const float* w3b = (const float*)d_in[19];

    float *xd0,*xd1,*ll1,*h1,*ll40,*mask1,*upm1,*cam1,*wm1;
    float *xa,*h2,*ll80,*mask2,*upm2,*cam2,*wm2,*xb,*h3,*thr;
    uint32_t *px32,*cat1,*feat1,*feat0;
    __nv_bfloat16 *w2h,*w2l,*p1h,*p1l,*p2h,*p2l,*p3h,*p3l;
    cudaGetSymbolAddress((void**)&xd0,g_xd0);   cudaGetSymbolAddress((void**)&xd1,g_xd1);
    cudaGetSymbolAddress((void**)&ll1,g_ll1);   cudaGetSymbolAddress((void**)&h1,g_h1);
    cudaGetSymbolAddress((void**)&ll40,g_ll40); cudaGetSymbolAddress((void**)&mask1,g_mask1);
    cudaGetSymbolAddress((void**)&upm1,g_upm1); cudaGetSymbolAddress((void**)&cam1,g_cam1);
    cudaGetSymbolAddress((void**)&wm1,g_wm1);   cudaGetSymbolAddress((void**)&xa,g_xa);
    cudaGetSymbolAddress((void**)&h2,g_h2);     cudaGetSymbolAddress((void**)&ll80,g_ll80);
    cudaGetSymbolAddress((void**)&mask2,g_mask2); cudaGetSymbolAddress((void**)&upm2,g_upm2);
    cudaGetSymbolAddress((void**)&cam2,g_cam2); cudaGetSymbolAddress((void**)&wm2,g_wm2);
    cudaGetSymbolAddress((void**)&xb,g_xb);     cudaGetSymbolAddress((void**)&h3,g_h3);
    cudaGetSymbolAddress((void**)&thr,g_thr);
    cudaGetSymbolAddress((void**)&px32,g_px32); cudaGetSymbolAddress((void**)&cat1,g_cat1);
    cudaGetSymbolAddress((void**)&feat1,g_feat1); cudaGetSymbolAddress((void**)&feat0,g_feat0);
    cudaGetSymbolAddress((void**)&w2h,g_w2h);   cudaGetSymbolAddress((void**)&w2l,g_w2l);
    cudaGetSymbolAddress((void**)&p1h,g_u1h);   cudaGetSymbolAddress((void**)&p1l,g_u1l);
    cudaGetSymbolAddress((void**)&p2h,g_u2h);   cudaGetSymbolAddress((void**)&p2l,g_u2l);
    cudaGetSymbolAddress((void**)&p3h,g_u3h);   cudaGetSymbolAddress((void**)&p3l,g_u3l);

    cudaFuncSetAttribute(conv_hmma<2,4,3,1>, cudaFuncAttributeMaxDynamicSharedMemorySize, CONV_SMEM);
    cudaFuncSetAttribute(conv_hmma<1,3,3,0>, cudaFuncAttributeMaxDynamicSharedMemorySize, CONV_SMEM);
    cudaFuncSetAttribute(conv_hmma<1,3,2,0>, cudaFuncAttributeMaxDynamicSharedMemorySize, CONV_SMEM);

    // launches 1-3 (profiled slot 4 = conv2)
    { int t=1152*2208; pack_w_k<<<dim3((t+255)/256,9),256>>>(c2w, w2h, w2l, 1104, 2208, 2208, 19872, t); }
    { int t=BATCH*2208*320; pack_x_k<<<(t+255)/256,256>>>(x32, px32, t); }
    zero6_k<<<(BATCH*552*1280+255)/256,256>>>(xd0, BATCH*1104*320, xd1, BATCH*552*1280,
                                              ll1, BATCH*1280, h1, BATCH*3*1280,
                                              h2, BATCH*3*5120, h3, BATCH*3*20480);

    // 4: conv2 (edge): 2208->1104, 10x32, MT4 Mtiles=9, S=8, 3-term, batch-folded N (BHW=1280, 10 exact tiles)
    conv_hmma<2,4,3,1><<<dim3(10, 9*8), 256, CONV_SMEM>>>(w2h, w2l, px32, xd0,
        2208, 2208, 1104, 10, 32, 1280, 19872, 8, nullptr, nullptr, 0);
    finalize_big<<<(BATCH*1104*320+255)/256,256>>>(xd0, c2b, nullptr, 1104, 320, 0, BATCH*1104*320);

    { int t=640*1504;  pack_w_k<<<dim3((t+255)/256,9),256>>>(u1w, p1h, p1l, 552, 1488, 1504, 13536, t); }
    { int t = BATCH*1488*20*64;
      feat_pack_k<<<(t+255)/256,256>>>(xd0, x16, nullptr, nullptr, cat1, 1104, 384, 20, 64, t); }
    // up1 (reflect): 1488->552, MT3 Mtiles=6 (576 rows), S=4, 3-term
    conv_hmma<1,3,3,0><<<dim3(10, 6*4, BATCH), 256, CONV_SMEM>>>(p1h, p1l, cat1, xd1,
        1488, 1504, 552, 20, 64, 1280, 13536, 4, nullptr, nullptr, 0);
    finalize_big<<<(BATCH*552*1280+255)/256,256>>>(xd1, u1b, nullptr, 552, 1280, 1, BATCH*552*1280);
    conv_small_part<1,2><<<dim3(10,12,BATCH),128>>>(xd1, wllw, ll1, 552, 12, 20, 64);
    conv_small_part<3,0><<<dim3(10,12,BATCH),128>>>(xd1, w1w, h1, 552, 12, 20, 64);
    finalize_small<<<(BATCH*1280+255)/256,256>>>(ll1, wllb, nullptr, 1, 20, 64, 8.f, BATCH*1280);
    finalize_small<<<(BATCH*3*1280+255)/256,256>>>(h1, w1b, nullptr, 3, 20, 64, 4.f, BATCH*3*1280);
    idwt_k<<<dim3(5,1,BATCH),256>>>(ll1, h1, ll40, 20, 64);
    minmax_k<<<1,1024>>>(ll40, BATCH*40*128, thr);
    mask_k<<<dim3(5,1,BATCH),256>>>(h1, thr, mask1, 20, 64);
    pool_coarse_k<<<dim3(5,1,BATCH),256>>>(mask1, upm1, 20, 64);
    pool_fine_k<<<dim3(20,1,BATCH),256>>>(mask1, cam1, wm1, 20, 64);

    { int t=384*768;   pack_w_k<<<dim3((t+255)/256,9),256>>>(u2w, p2h, p2l, 276, 744, 768, 6912, t); }
    { int t = BATCH*744*40*128;
      feat_pack_k<<<(t+255)/256,256>>>(xd1, x8, upm1, cam1, feat1, 552, 192, 40, 128, t); }
    // up2 (reflect): 744->276, MT3 Mtiles=3 (288 rows), S=1, fused epilogue, 3-term
    conv_hmma<1,3,3,0><<<dim3(40, 3, BATCH), 256, CONV_SMEM>>>(p2h, p2l, feat1, xa,
        744, 768, 276, 40, 128, 5120, 6912, 1, u2b, wm1, 1);
    conv_small_part<3,0><<<dim3(40,8,BATCH),128>>>(xa, w2w, h2, 276, 8, 40, 128);
    finalize_small<<<(BATCH*3*5120+255)/256,256>>>(h2, w2b, mask1, 3, 40, 128, 2.f, BATCH*3*5120);
    idwt_k<<<dim3(20,1,BATCH),256>>>(ll40, h2, ll80, 40, 128);
    minmax_k<<<1,1024>>>(ll80, BATCH*80*256, thr);
    mask_k<<<dim3(20,1,BATCH),256>>>(h2, thr, mask2, 40, 128);
    pool_coarse_k<<<dim3(20,1,BATCH),256>>>(mask2, upm2, 40, 128);
    pool_fine_k<<<dim3(80,1,BATCH),256>>>(mask2, cam2, wm2, 40, 128);

    { int t=256*384;   pack_w_k<<<dim3((t+255)/256,9),256>>>(u3w, p3h, p3l, 138, 372, 384, 3456, t); }
    { int t = BATCH*372*80*256;
      feat_pack_k<<<(t+255)/256,256>>>(xa, x4, upm2, cam2, feat0, 276, 96, 80, 256, t); }
    // up3 (reflect): 372->138, MT3 Mtiles=2 (192 rows), S=1, fused epilogue, 2-TERM
    conv_hmma<1,3,2,0><<<dim3(160, 2, BATCH), 256, CONV_SMEM>>>(p3h, p3l, feat0, xb,
        372, 384, 138, 80, 256, 20480, 3456, 1, u3b, wm2, 1);
    conv_small_part<3,0><<<dim3(160,4,BATCH),128>>>(xb, w3w, h3, 138, 4, 80, 256);
    finalize_small<<<(BATCH*3*20480+255)/256,256>>>(h3, w3b, mask2, 3, 80, 256, 1.f, BATCH*3*20480);
    idwt_k<<<dim3(80,1,BATCH),256>>>(ll80, h3, (float*)d_out, 80, 256);
}